// round 2
// baseline (speedup 1.0000x reference)
#include <cuda_runtime.h>
#include <math.h>

#define B_ 8
#define N_ 8192
#define K_ 32
#define D_ 64
#define STRIDE 72          // smem row stride (floats) for edge-feature buffers

typedef unsigned long long ull;

// ---------------- shared memory layout (in floats) ----------------
#define OFF_W0T   0            // [129][64] transposed W0 (i-major)
#define OFF_W1T   8256         // [64][64]
#define OFF_W2T   12352        // [64][64]
#define OFF_B0    16448        // 64
#define OFF_B1    16512        // 64
#define OFF_B2    16576        // 64
#define OFF_SELF  16640        // 8 nodes x 64  (emb*mask)
#define OFF_SELFC 17152        // 8 nodes x 64  (b0 + self-part of layer0)
#define OFF_DIST  17664        // 256
#define OFF_VALID 17920        // 256
#define OFF_IDX   18176        // 256 ints
#define OFF_MASKF 18432        // 8
#define OFF_FACT  18440        // 8 (mask / n_valid)
#define OFF_SRC   18448        // 256 rows x STRIDE (gathered src; reused as H1)
#define OFF_H0    36880        // 256 rows x STRIDE (layer0 out; reused as partials)
#define SMEM_FLOATS 55312      // 221248 bytes

// ---------------- device scratch (no allocation allowed) ----------------
__device__ float g_upd[B_ * N_ * D_];
__device__ float g_sum[B_][D_];
__device__ float g_sqs[B_][D_];
__device__ float g_cnt[B_];

__device__ __forceinline__ float gelu_f(float x) {
    return 0.5f * x * (1.0f + erff(x * 0.7071067811865475f));
}

__device__ __forceinline__ ull pack2(float x) {
    ull r; asm("mov.b64 %0, {%1, %1};" : "=l"(r) : "f"(x)); return r;
}
__device__ __forceinline__ void ffma2(ull& d, ull a, ull b) {
    asm("fma.rn.f32x2 %0, %1, %2, %0;" : "+l"(d) : "l"(a), "l"(b));
}
__device__ __forceinline__ float2 unpack2(ull v) {
    float2 f; asm("mov.b64 {%0, %1}, %2;" : "=f"(f.x), "=f"(f.y) : "l"(v)); return f;
}

// acc[r][p] += sum_i in[ebase+r][i] * Wt[i][d0 + 2p .. 2p+1]  (64-dim inner, f32x2)
__device__ __forceinline__ void mm2(const float* __restrict__ sIn,
                                    const float* __restrict__ sWt,
                                    int ebase, int d0, ull acc[4][4]) {
#define MM_STEP(IIDX, COMP) do {                                               \
        const ulonglong2 wA = *(const ulonglong2*)(sWt + (i + IIDX) * 64 + d0);     \
        const ulonglong2 wB = *(const ulonglong2*)(sWt + (i + IIDX) * 64 + d0 + 4); \
        ull a0 = pack2(f0.COMP), a1 = pack2(f1.COMP);                          \
        ull a2 = pack2(f2.COMP), a3 = pack2(f3.COMP);                          \
        ffma2(acc[0][0], a0, wA.x); ffma2(acc[0][1], a0, wA.y);                \
        ffma2(acc[0][2], a0, wB.x); ffma2(acc[0][3], a0, wB.y);                \
        ffma2(acc[1][0], a1, wA.x); ffma2(acc[1][1], a1, wA.y);                \
        ffma2(acc[1][2], a1, wB.x); ffma2(acc[1][3], a1, wB.y);                \
        ffma2(acc[2][0], a2, wA.x); ffma2(acc[2][1], a2, wA.y);                \
        ffma2(acc[2][2], a2, wB.x); ffma2(acc[2][3], a2, wB.y);                \
        ffma2(acc[3][0], a3, wA.x); ffma2(acc[3][1], a3, wA.y);                \
        ffma2(acc[3][2], a3, wB.x); ffma2(acc[3][3], a3, wB.y);                \
    } while (0)

#pragma unroll 2
    for (int i = 0; i < 64; i += 4) {
        float4 f0 = *(const float4*)(sIn + (ebase + 0) * STRIDE + i);
        float4 f1 = *(const float4*)(sIn + (ebase + 1) * STRIDE + i);
        float4 f2 = *(const float4*)(sIn + (ebase + 2) * STRIDE + i);
        float4 f3 = *(const float4*)(sIn + (ebase + 3) * STRIDE + i);
        MM_STEP(0, x);
        MM_STEP(1, y);
        MM_STEP(2, z);
        MM_STEP(3, w);
    }
#undef MM_STEP
}

// gelu over a row of 4 acc pairs -> two float4 stores
__device__ __forceinline__ void gelu_store(float* dst, const ull a[4]) {
    float2 v0 = unpack2(a[0]), v1 = unpack2(a[1]);
    float2 v2 = unpack2(a[2]), v3 = unpack2(a[3]);
    float4 o0, o1;
    o0.x = gelu_f(v0.x); o0.y = gelu_f(v0.y); o0.z = gelu_f(v1.x); o0.w = gelu_f(v1.y);
    o1.x = gelu_f(v2.x); o1.y = gelu_f(v2.y); o1.z = gelu_f(v3.x); o1.w = gelu_f(v3.y);
    *(float4*)(dst)     = o0;
    *(float4*)(dst + 4) = o1;
}

__global__ void __launch_bounds__(512, 1)
mpnn_msg_kernel(const float* __restrict__ emb,
                const float* __restrict__ dists,
                const int*   __restrict__ eidx,
                const float* __restrict__ mask,
                const float* __restrict__ W0, const float* __restrict__ b0,
                const float* __restrict__ W1, const float* __restrict__ b1,
                const float* __restrict__ W2, const float* __restrict__ b2)
{
    extern __shared__ float sm[];
    const int tid = threadIdx.x;

    // load weights transposed (one-time per block)
    for (int p = tid; p < 129 * 64; p += 512) {
        int i = p >> 6, d = p & 63;
        sm[OFF_W0T + p] = W0[d * 129 + i];
    }
    for (int p = tid; p < 64 * 64; p += 512) {
        int i = p >> 6, d = p & 63;
        sm[OFF_W1T + p] = W1[d * 64 + i];
        sm[OFF_W2T + p] = W2[d * 64 + i];
    }
    if (tid < 64) {
        sm[OFF_B0 + tid] = b0[tid];
        sm[OFF_B1 + tid] = b1[tid];
        sm[OFF_B2 + tid] = b2[tid];
    }
    __syncthreads();

    int* sIdx = reinterpret_cast<int*>(sm + OFF_IDX);
    const int d0    = (tid & 7) << 3;    // output channel base (8 contiguous)
    const int g     = tid >> 3;          // edge group 0..63
    const int ebase = g << 2;            // 4 edges per thread
    const int snode = g >> 3;            // node slot 0..7

    const int totalIter = (B_ * N_) >> 3;  // 8 nodes per iteration
    for (int iter = blockIdx.x; iter < totalIter; iter += gridDim.x) {
        const int bn0 = iter << 3;
        const int b   = bn0 >> 13;          // /N_
        const int n0  = bn0 & (N_ - 1);

        // ---- phase 1: per-edge meta + self embedding ----
        {
            // self embedding: 8 nodes x 64, one element per thread
            int s = tid >> 6, c = tid & 63;
            int row = b * N_ + n0 + s;
            sm[OFF_SELF + tid] = emb[row * 64 + c] * mask[row];
        }
        if (tid < 256) {
            int s = tid >> 5;
            int off = (b * N_ + n0 + s) * K_ + (tid & 31);
            int idx = eidx[off];
            sm[OFF_VALID + tid] = (idx != -1) ? 1.0f : 0.0f;
            sIdx[tid] = (idx == -1) ? 0 : idx;
            sm[OFF_DIST + tid] = dists[off];
        }
        if (tid < 8) sm[OFF_MASKF + tid] = mask[b * N_ + n0 + tid];
        __syncthreads();

        // ---- phase 2: gather src feats + self contribution + n_valid ----
#pragma unroll
        for (int q = 0; q < 8; q++) {
            int pos = tid + q * 512;         // 0..4095
            int eb = pos >> 4, c4 = pos & 15;
            int row = b * N_ + sIdx[eb];
            float m = mask[row];
            float4 v = reinterpret_cast<const float4*>(emb)[row * 16 + c4];
            v.x *= m; v.y *= m; v.z *= m; v.w *= m;
            *reinterpret_cast<float4*>(sm + OFF_SRC + eb * STRIDE + c4 * 4) = v;
        }
        {
            int s = tid >> 6, d = tid & 63;
            float a = sm[OFF_B0 + d];
            const float* sp = sm + OFF_SELF + s * 64;
            const float* wp = sm + OFF_W0T + 64 * 64 + d;
#pragma unroll 8
            for (int i = 0; i < 64; i++) a = fmaf(sp[i], wp[i * 64], a);
            sm[OFF_SELFC + tid] = a;
        }
        if (tid < 8) {
            float c = 0.0f;
            for (int e = 0; e < 32; e++) c += sm[OFF_VALID + tid * 32 + e];
            if (c == 0.0f) c = 1.0f;
            sm[OFF_FACT + tid] = sm[OFF_MASKF + tid] / c;
        }
        __syncthreads();

        // ---- layer 0: src(64) part + dist, self part prefolded ----
        ull acc[4][4];
        {
            const ulonglong2 wc0 = *(const ulonglong2*)(sm + OFF_W0T + 128 * 64 + d0);
            const ulonglong2 wc1 = *(const ulonglong2*)(sm + OFF_W0T + 128 * 64 + d0 + 4);
            const ulonglong2 s01 = *(const ulonglong2*)(sm + OFF_SELFC + snode * 64 + d0);
            const ulonglong2 s23 = *(const ulonglong2*)(sm + OFF_SELFC + snode * 64 + d0 + 4);
#pragma unroll
            for (int r = 0; r < 4; r++) {
                ull dd = pack2(sm[OFF_DIST + ebase + r]);
                acc[r][0] = s01.x; acc[r][1] = s01.y;
                acc[r][2] = s23.x; acc[r][3] = s23.y;
                ffma2(acc[r][0], dd, wc0.x); ffma2(acc[r][1], dd, wc0.y);
                ffma2(acc[r][2], dd, wc1.x); ffma2(acc[r][3], dd, wc1.y);
            }
            mm2(sm + OFF_SRC, sm + OFF_W0T, ebase, d0, acc);
#pragma unroll
            for (int r = 0; r < 4; r++)
                gelu_store(sm + OFF_H0 + (ebase + r) * STRIDE + d0, acc[r]);
        }
        __syncthreads();

        // ---- layer 1: H0 -> H1 (reuses SRC region) ----
        {
            const ulonglong2 b01 = *(const ulonglong2*)(sm + OFF_B1 + d0);
            const ulonglong2 b23 = *(const ulonglong2*)(sm + OFF_B1 + d0 + 4);
#pragma unroll
            for (int r = 0; r < 4; r++) {
                acc[r][0] = b01.x; acc[r][1] = b01.y;
                acc[r][2] = b23.x; acc[r][3] = b23.y;
            }
            mm2(sm + OFF_H0, sm + OFF_W1T, ebase, d0, acc);
#pragma unroll
            for (int r = 0; r < 4; r++)
                gelu_store(sm + OFF_SRC + (ebase + r) * STRIDE + d0, acc[r]);
        }
        __syncthreads();

        // ---- layer 2 + masked per-thread partial aggregation ----
        {
            const ulonglong2 b01 = *(const ulonglong2*)(sm + OFF_B2 + d0);
            const ulonglong2 b23 = *(const ulonglong2*)(sm + OFF_B2 + d0 + 4);
#pragma unroll
            for (int r = 0; r < 4; r++) {
                acc[r][0] = b01.x; acc[r][1] = b01.y;
                acc[r][2] = b23.x; acc[r][3] = b23.y;
            }
            mm2(sm + OFF_SRC, sm + OFF_W2T, ebase, d0, acc);

            float p[8];
#pragma unroll
            for (int j = 0; j < 8; j++) p[j] = 0.0f;
#pragma unroll
            for (int r = 0; r < 4; r++) {
                float v = sm[OFF_VALID + ebase + r];
                float2 v0 = unpack2(acc[r][0]), v1 = unpack2(acc[r][1]);
                float2 v2 = unpack2(acc[r][2]), v3 = unpack2(acc[r][3]);
                p[0] = fmaf(gelu_f(v0.x), v, p[0]);
                p[1] = fmaf(gelu_f(v0.y), v, p[1]);
                p[2] = fmaf(gelu_f(v1.x), v, p[2]);
                p[3] = fmaf(gelu_f(v1.y), v, p[3]);
                p[4] = fmaf(gelu_f(v2.x), v, p[4]);
                p[5] = fmaf(gelu_f(v2.y), v, p[5]);
                p[6] = fmaf(gelu_f(v3.x), v, p[6]);
                p[7] = fmaf(gelu_f(v3.y), v, p[7]);
            }
            // partials: row g (reuses H0 region, dead after layer 1)
            *(float4*)(sm + OFF_H0 + g * STRIDE + d0)     = make_float4(p[0], p[1], p[2], p[3]);
            *(float4*)(sm + OFF_H0 + g * STRIDE + d0 + 4) = make_float4(p[4], p[5], p[6], p[7]);
        }
        __syncthreads();

        // ---- final reduce over 8 groups per node, write upd ----
        {
            int s = tid >> 6, d = tid & 63;
            float msg = 0.0f;
#pragma unroll
            for (int gg = 0; gg < 8; gg++)
                msg += sm[OFF_H0 + (s * 8 + gg) * STRIDE + d];
            float upd = sm[OFF_SELF + s * 64 + d] + msg * sm[OFF_FACT + s];
            g_upd[(b * N_ + n0 + s) * 64 + d] = upd;
        }
        __syncthreads();
    }
}

__global__ void zero_stats_kernel() {
    int t = threadIdx.x;
    if (t < B_ * D_) {
        reinterpret_cast<float*>(g_sum)[t] = 0.0f;
        reinterpret_cast<float*>(g_sqs)[t] = 0.0f;
    }
    if (t < B_) g_cnt[t] = 0.0f;
}

__global__ void __launch_bounds__(256)
stats_kernel(const float* __restrict__ mask) {
    __shared__ float sh[512];
    const int b = blockIdx.y;
    const int chunk = blockIdx.x;      // 16 chunks of 512 rows
    const int tid = threadIdx.x;       // 256
    const int d = tid & 63, ro = tid >> 6;
    float s1 = 0.0f, s2 = 0.0f;
    const int base = (b * N_ + chunk * 512) * 64;
    for (int q = 0; q < 128; q++) {
        float v = g_upd[base + (q * 4 + ro) * 64 + d];
        s1 += v;
        s2 = fmaf(v, v, s2);
    }
    sh[tid] = s1;
    sh[256 + tid] = s2;
    __syncthreads();
    if (tid < 64) {
        float a = sh[tid] + sh[tid + 64] + sh[tid + 128] + sh[tid + 192];
        float c = sh[256 + tid] + sh[256 + tid + 64] + sh[256 + tid + 128] + sh[256 + tid + 192];
        atomicAdd(&g_sum[b][tid], a);
        atomicAdd(&g_sqs[b][tid], c);
    }
    __syncthreads();
    // mask count
    float mc = mask[b * N_ + chunk * 512 + tid] + mask[b * N_ + chunk * 512 + 256 + tid];
    sh[tid] = mc;
    __syncthreads();
    for (int st = 128; st >= 1; st >>= 1) {
        if (tid < st) sh[tid] += sh[tid + st];
        __syncthreads();
    }
    if (tid == 0) atomicAdd(&g_cnt[b], sh[0]);
}

__global__ void __launch_bounds__(256)
norm_kernel(const float* __restrict__ mask,
            const float* __restrict__ scale,
            const float* __restrict__ shift,
            float* __restrict__ out) {
    int t = blockIdx.x * 256 + threadIdx.x;
    for (int e = t; e < B_ * N_ * D_; e += gridDim.x * 256) {
        int d  = e & 63;
        int bn = e >> 6;
        int b  = bn >> 13;
        float cnt = g_cnt[b];
        if (cnt == 0.0f) cnt = 1.0f;
        float s1 = g_sum[b][d], s2 = g_sqs[b][d];
        float mean = s1 / cnt;
        float var  = (s2 - 2.0f * mean * s1 + (float)N_ * mean * mean) / cnt;
        float rstd = rsqrtf(var + 1e-5f);
        float v = (g_upd[e] - mean) * rstd;
        out[e] = fmaf(v, scale[d], shift[d]) * mask[bn];
    }
}

extern "C" void kernel_launch(void* const* d_in, const int* in_sizes, int n_in,
                              void* d_out, int out_size) {
    const float* emb   = (const float*)d_in[0];
    const float* dists = (const float*)d_in[1];
    const int*   eidx  = (const int*)d_in[2];
    const float* mask  = (const float*)d_in[3];
    const float* W0 = (const float*)d_in[4];
    const float* b0 = (const float*)d_in[5];
    const float* W1 = (const float*)d_in[6];
    const float* b1 = (const float*)d_in[7];
    const float* W2 = (const float*)d_in[8];
    const float* b2 = (const float*)d_in[9];
    const float* scale = (const float*)d_in[10];
    const float* shift = (const float*)d_in[11];
    float* out = (float*)d_out;

    int smc = 148;
    cudaDeviceGetAttribute(&smc, cudaDevAttrMultiProcessorCount, 0);

    cudaFuncSetAttribute(mpnn_msg_kernel,
                         cudaFuncAttributeMaxDynamicSharedMemorySize,
                         SMEM_FLOATS * 4);

    zero_stats_kernel<<<1, 512>>>();
    mpnn_msg_kernel<<<smc, 512, SMEM_FLOATS * 4>>>(emb, dists, eidx, mask,
                                                   W0, b0, W1, b1, W2, b2);
    stats_kernel<<<dim3(16, 8), 256>>>(mask);
    norm_kernel<<<4096, 256>>>(mask, scale, shift, out);
}

// round 4
// speedup vs baseline: 1.6495x; 1.6495x over previous
#include <cuda_runtime.h>
#include <math.h>
#include <cstdint>

#define B_ 8
#define N_ 8192
#define K_ 32
#define D_ 64

// ---------------- dynamic smem byte offsets ----------------
#define OFF_BFRAG   0          // B fragments: 24 combos x (hi 1024B + lo 1024B)
#define OFF_AG      49152      // 128 rows x 68 f32 (gathered src; reused as MSG)
#define OFF_W0SELF  83968      // [64 i][64 d] f32 (self half of W0, i-major)
#define OFF_SSELF   100352     // 4 x 64 f32 (emb*mask per node)
#define OFF_SELFC   101376     // 4 x 64 f32 (b0 + self-part of layer 0)
#define OFF_SDIST   102400     // 128 f32
#define OFF_SVALID  102912     // 128 f32
#define OFF_SIDX    103424     // 128 i32
#define OFF_WD      103936     // 64 f32 (W0[:,128] dist column)
#define OFF_B1S     104192     // 64 f32
#define OFF_B2S     104448     // 64 f32
#define OFF_FACT    104704     // 4 f32
#define SMEM_BYTES  104832

// ---------------- device scratch ----------------
__device__ float g_upd[B_ * N_ * D_];
__device__ float g_sum[B_][D_];
__device__ float g_sqs[B_][D_];
__device__ float g_cnt[B_];

__device__ __forceinline__ float gelu_f(float x) {
    return 0.5f * x * (1.0f + erff(x * 0.7071067811865475f));
}
// pack two floats to bf16x2 (first arg -> low half)
__device__ __forceinline__ uint32_t pack_bf16x2(float lo, float hi) {
    uint32_t r;
    asm("cvt.rn.bf16x2.f32 %0, %1, %2;" : "=r"(r) : "f"(hi), "f"(lo));
    return r;
}
__device__ __forceinline__ void split_pair(float x0, float x1, uint32_t& h, uint32_t& l) {
    h = pack_bf16x2(x0, x1);
    float f0 = __uint_as_float(h << 16);
    float f1 = __uint_as_float(h & 0xFFFF0000u);
    l = pack_bf16x2(x0 - f0, x1 - f1);
}

__device__ __forceinline__ void mma_bf16(float* d,
                                         uint32_t a0, uint32_t a1, uint32_t a2, uint32_t a3,
                                         uint32_t b0, uint32_t b1) {
    asm volatile(
        "mma.sync.aligned.m16n8k16.row.col.f32.bf16.bf16.f32 "
        "{%0,%1,%2,%3}, {%4,%5,%6,%7}, {%8,%9}, {%0,%1,%2,%3};"
        : "+f"(d[0]), "+f"(d[1]), "+f"(d[2]), "+f"(d[3])
        : "r"(a0), "r"(a1), "r"(a2), "r"(a3), "r"(b0), "r"(b1));
}

__global__ void __launch_bounds__(256, 2)
mpnn_msg_kernel(const float* __restrict__ emb,
                const float* __restrict__ dists,
                const int*   __restrict__ eidx,
                const float* __restrict__ mask,
                const float* __restrict__ W0, const float* __restrict__ b0,
                const float* __restrict__ W1, const float* __restrict__ b1,
                const float* __restrict__ W2, const float* __restrict__ b2)
{
    extern __shared__ char smb[];
    float* smf = reinterpret_cast<float*>(smb);
    const int tid = threadIdx.x;
    const int w = tid >> 5, lane = tid & 31;
    const int lq = lane >> 2;      // 0..7 (row group)
    const int lr = lane & 3;       // 0..3 (col pair group)

    // ---- one-time staging: B fragments, W0self, wd, biases ----
    // combo c = l*8 + t ; block at OFF_BFRAG + c*2048 ; hi at +0, lo at +1024
    for (int c = w; c < 24; c += 8) {
        const int l = c >> 3, t = c & 7;
        const float* W = (l == 0) ? W0 : (l == 1) ? W1 : W2;
        const int stride = (l == 0) ? 129 : 64;
        const int n = t * 8 + lq;
        uint32_t hi[8], lo[8];
#pragma unroll
        for (int j = 0; j < 8; j++) {
            int s = j >> 1, rsel = j & 1;
            int k = 16 * s + 8 * rsel + 2 * lr;
            float x0 = W[n * stride + k];
            float x1 = W[n * stride + k + 1];
            split_pair(x0, x1, hi[j], lo[j]);
        }
        uint4* dh = reinterpret_cast<uint4*>(smb + OFF_BFRAG + c * 2048 + lane * 32);
        uint4* dl = reinterpret_cast<uint4*>(smb + OFF_BFRAG + c * 2048 + 1024 + lane * 32);
        dh[0] = make_uint4(hi[0], hi[1], hi[2], hi[3]);
        dh[1] = make_uint4(hi[4], hi[5], hi[6], hi[7]);
        dl[0] = make_uint4(lo[0], lo[1], lo[2], lo[3]);
        dl[1] = make_uint4(lo[4], lo[5], lo[6], lo[7]);
    }
    for (int p = tid; p < 4096; p += 256) {
        int i = p >> 6, d = p & 63;
        smf[OFF_W0SELF / 4 + p] = W0[d * 129 + 64 + i];
    }
    if (tid < 64) {
        smf[OFF_WD / 4 + tid]  = W0[tid * 129 + 128];
        smf[OFF_B1S / 4 + tid] = b1[tid];
        smf[OFF_B2S / 4 + tid] = b2[tid];
    }
    __syncthreads();

    int* sIdx = reinterpret_cast<int*>(smb + OFF_SIDX);
    const int totalTiles = (B_ * N_) / 4;   // 4 nodes x 32 edges = 128 rows/tile

    for (int tile = blockIdx.x; tile < totalTiles; tile += gridDim.x) {
        const int bn0 = tile << 2;
        const int b   = bn0 >> 13;
        const int n0  = bn0 & (N_ - 1);
        const int bbase = b * N_;

        // ---- phase 1: edge meta + masked self embedding ----
        if (tid < 128) {
            int off = (bbase + n0 + (tid >> 5)) * K_ + (tid & 31);
            int idx = eidx[off];
            smf[OFF_SVALID / 4 + tid] = (idx != -1) ? 1.0f : 0.0f;
            sIdx[tid] = (idx == -1) ? 0 : idx;
            smf[OFF_SDIST / 4 + tid] = dists[off];
        }
        {
            int s = tid >> 6, i = tid & 63;
            int row = bbase + n0 + s;
            smf[OFF_SSELF / 4 + tid] = emb[row * 64 + i] * mask[row];
        }
        __syncthreads();

        // ---- phase 2: gather src rows + selfC + fact ----
#pragma unroll
        for (int q = 0; q < 8; q++) {
            int p = tid + q * 256;
            int row = p >> 4, c4 = p & 15;
            int gr = bbase + sIdx[row];
            float m = mask[gr];
            float4 v = reinterpret_cast<const float4*>(emb)[(size_t)gr * 16 + c4];
            v.x *= m; v.y *= m; v.z *= m; v.w *= m;
            *reinterpret_cast<float4*>(smf + OFF_AG / 4 + row * 68 + c4 * 4) = v;
        }
        {
            int s = tid >> 6, d = tid & 63;
            float a = b0[d];
            const float* sv = smf + OFF_SSELF / 4 + s * 64;
            const float* wp = smf + OFF_W0SELF / 4 + d;
#pragma unroll 8
            for (int i = 0; i < 64; i++) a = fmaf(sv[i], wp[i * 64], a);
            smf[OFF_SELFC / 4 + tid] = a;
        }
        if (tid < 4) {
            float c = 0.0f;
            for (int e = 0; e < 32; e++) c += smf[OFF_SVALID / 4 + tid * 32 + e];
            if (c == 0.0f) c = 1.0f;
            smf[OFF_FACT / 4 + tid] = mask[bbase + n0 + tid] / c;
        }
        __syncthreads();

        // ---- build layer-0 A fragments from gathered rows ----
        const int r0 = (w << 4) + lq;      // warp's first row + row group
        uint32_t ah[4][4], al[4][4];
        {
            const float* ag = smf + OFF_AG / 4;
#pragma unroll
            for (int s = 0; s < 4; s++) {
                int cb2 = 16 * s + 2 * lr;
                float2 p00 = *(const float2*)(ag + r0 * 68 + cb2);
                float2 p10 = *(const float2*)(ag + (r0 + 8) * 68 + cb2);
                float2 p01 = *(const float2*)(ag + r0 * 68 + cb2 + 8);
                float2 p11 = *(const float2*)(ag + (r0 + 8) * 68 + cb2 + 8);
                split_pair(p00.x, p00.y, ah[s][0], al[s][0]);
                split_pair(p10.x, p10.y, ah[s][1], al[s][1]);
                split_pair(p01.x, p01.y, ah[s][2], al[s][2]);
                split_pair(p11.x, p11.y, ah[s][3], al[s][3]);
            }
        }

        // ---- 3 layers of MMA + epilogue (activations stay in registers) ----
#pragma unroll
        for (int l = 0; l < 3; l++) {
            float dacc[8][4];
#pragma unroll
            for (int t = 0; t < 8; t++)
#pragma unroll
                for (int j = 0; j < 4; j++) dacc[t][j] = 0.0f;

#pragma unroll
            for (int t = 0; t < 8; t++) {
                const char* base = smb + OFF_BFRAG + (l * 8 + t) * 2048;
                const uint4* bph = reinterpret_cast<const uint4*>(base + lane * 32);
                uint4 h0 = bph[0], h1 = bph[1];
                mma_bf16(dacc[t], ah[0][0], ah[0][1], ah[0][2], ah[0][3], h0.x, h0.y);
                mma_bf16(dacc[t], ah[1][0], ah[1][1], ah[1][2], ah[1][3], h0.z, h0.w);
                mma_bf16(dacc[t], ah[2][0], ah[2][1], ah[2][2], ah[2][3], h1.x, h1.y);
                mma_bf16(dacc[t], ah[3][0], ah[3][1], ah[3][2], ah[3][3], h1.z, h1.w);
                mma_bf16(dacc[t], al[0][0], al[0][1], al[0][2], al[0][3], h0.x, h0.y);
                mma_bf16(dacc[t], al[1][0], al[1][1], al[1][2], al[1][3], h0.z, h0.w);
                mma_bf16(dacc[t], al[2][0], al[2][1], al[2][2], al[2][3], h1.x, h1.y);
                mma_bf16(dacc[t], al[3][0], al[3][1], al[3][2], al[3][3], h1.z, h1.w);
                const uint4* bpl = reinterpret_cast<const uint4*>(base + 1024 + lane * 32);
                uint4 l0v = bpl[0], l1v = bpl[1];
                mma_bf16(dacc[t], ah[0][0], ah[0][1], ah[0][2], ah[0][3], l0v.x, l0v.y);
                mma_bf16(dacc[t], ah[1][0], ah[1][1], ah[1][2], ah[1][3], l0v.z, l0v.w);
                mma_bf16(dacc[t], ah[2][0], ah[2][1], ah[2][2], ah[2][3], l1v.x, l1v.y);
                mma_bf16(dacc[t], ah[3][0], ah[3][1], ah[3][2], ah[3][3], l1v.z, l1v.w);
            }

            if (l < 2) {
                const int node = w >> 1;
                float dr0 = 0.0f, dr1 = 0.0f;
                if (l == 0) {
                    dr0 = smf[OFF_SDIST / 4 + r0];
                    dr1 = smf[OFF_SDIST / 4 + r0 + 8];
                }
#pragma unroll
                for (int s = 0; s < 4; s++) {
                    float g[8];
#pragma unroll
                    for (int half = 0; half < 2; half++) {
                        const int t = 2 * s + half;
                        const int c0 = 8 * t + 2 * lr;
                        float a0, a1;
                        if (l == 0) {
                            float sc0 = smf[OFF_SELFC / 4 + node * 64 + c0];
                            float sc1 = smf[OFF_SELFC / 4 + node * 64 + c0 + 1];
                            float wd0 = smf[OFF_WD / 4 + c0];
                            float wd1 = smf[OFF_WD / 4 + c0 + 1];
                            g[4 * half + 0] = gelu_f(dacc[t][0] + sc0 + dr0 * wd0);
                            g[4 * half + 1] = gelu_f(dacc[t][1] + sc1 + dr0 * wd1);
                            g[4 * half + 2] = gelu_f(dacc[t][2] + sc0 + dr1 * wd0);
                            g[4 * half + 3] = gelu_f(dacc[t][3] + sc1 + dr1 * wd1);
                        } else {
                            a0 = smf[OFF_B1S / 4 + c0];
                            a1 = smf[OFF_B1S / 4 + c0 + 1];
                            g[4 * half + 0] = gelu_f(dacc[t][0] + a0);
                            g[4 * half + 1] = gelu_f(dacc[t][1] + a1);
                            g[4 * half + 2] = gelu_f(dacc[t][2] + a0);
                            g[4 * half + 3] = gelu_f(dacc[t][3] + a1);
                        }
                    }
                    // repack: D tiles (2s, 2s+1) -> next-layer A k-tile s
                    split_pair(g[0], g[1], ah[s][0], al[s][0]);
                    split_pair(g[2], g[3], ah[s][1], al[s][1]);
                    split_pair(g[4], g[5], ah[s][2], al[s][2]);
                    split_pair(g[6], g[7], ah[s][3], al[s][3]);
                }
            } else {
                // layer 2: bias + gelu + valid mask -> MSG (reuses AG region)
                float v0 = smf[OFF_SVALID / 4 + r0];
                float v1 = smf[OFF_SVALID / 4 + r0 + 8];
                float* ag = smf + OFF_AG / 4;
#pragma unroll
                for (int t = 0; t < 8; t++) {
                    const int c0 = 8 * t + 2 * lr;
                    float bb0 = smf[OFF_B2S / 4 + c0];
                    float bb1 = smf[OFF_B2S / 4 + c0 + 1];
                    float2 m0, m1;
                    m0.x = gelu_f(dacc[t][0] + bb0) * v0;
                    m0.y = gelu_f(dacc[t][1] + bb1) * v0;
                    m1.x = gelu_f(dacc[t][2] + bb0) * v1;
                    m1.y = gelu_f(dacc[t][3] + bb1) * v1;
                    *reinterpret_cast<float2*>(ag + r0 * 68 + c0) = m0;
                    *reinterpret_cast<float2*>(ag + (r0 + 8) * 68 + c0) = m1;
                }
            }
        }
        __syncthreads();

        // ---- reduce 32 edges/node + write upd ----
        {
            int s = tid >> 6, d = tid & 63;
            float acc = 0.0f;
            const float* mp = smf + OFF_AG / 4 + (s * 32) * 68 + d;
#pragma unroll 8
            for (int e = 0; e < 32; e++) acc += mp[e * 68];
            float upd = smf[OFF_SSELF / 4 + s * 64 + d] + acc * smf[OFF_FACT / 4 + s];
            g_upd[(size_t)(bbase + n0 + s) * 64 + d] = upd;
        }
        __syncthreads();
    }
}

// ---------------- stats / norm ----------------
__global__ void zero_stats_kernel() {
    int t = threadIdx.x;
    if (t < B_ * D_) {
        reinterpret_cast<float*>(g_sum)[t] = 0.0f;
        reinterpret_cast<float*>(g_sqs)[t] = 0.0f;
    }
    if (t < B_) g_cnt[t] = 0.0f;
}

__global__ void __launch_bounds__(256)
stats_kernel(const float* __restrict__ mask) {
    __shared__ float sh[512];
    const int b = blockIdx.y;
    const int chunk = blockIdx.x;
    const int tid = threadIdx.x;
    const int d = tid & 63, ro = tid >> 6;
    float s1 = 0.0f, s2 = 0.0f;
    const int base = (b * N_ + chunk * 512) * 64;
    for (int q = 0; q < 128; q++) {
        float v = g_upd[base + (q * 4 + ro) * 64 + d];
        s1 += v;
        s2 = fmaf(v, v, s2);
    }
    sh[tid] = s1;
    sh[256 + tid] = s2;
    __syncthreads();
    if (tid < 64) {
        float a = sh[tid] + sh[tid + 64] + sh[tid + 128] + sh[tid + 192];
        float c = sh[256 + tid] + sh[256 + tid + 64] + sh[256 + tid + 128] + sh[256 + tid + 192];
        atomicAdd(&g_sum[b][tid], a);
        atomicAdd(&g_sqs[b][tid], c);
    }
    __syncthreads();
    float mc = mask[b * N_ + chunk * 512 + tid] + mask[b * N_ + chunk * 512 + 256 + tid];
    sh[tid] = mc;
    __syncthreads();
    for (int st = 128; st >= 1; st >>= 1) {
        if (tid < st) sh[tid] += sh[tid + st];
        __syncthreads();
    }
    if (tid == 0) atomicAdd(&g_cnt[b], sh[0]);
}

__global__ void __launch_bounds__(256)
norm_kernel(const float* __restrict__ mask,
            const float* __restrict__ scale,
            const float* __restrict__ shift,
            float* __restrict__ out) {
    int t = blockIdx.x * 256 + threadIdx.x;
    for (int e = t; e < B_ * N_ * D_; e += gridDim.x * 256) {
        int d  = e & 63;
        int bn = e >> 6;
        int b  = bn >> 13;
        float cnt = g_cnt[b];
        if (cnt == 0.0f) cnt = 1.0f;
        float s1 = g_sum[b][d], s2 = g_sqs[b][d];
        float mean = s1 / cnt;
        float var  = (s2 - 2.0f * mean * s1 + (float)N_ * mean * mean) / cnt;
        float rstd = rsqrtf(var + 1e-5f);
        float v = (g_upd[e] - mean) * rstd;
        out[e] = fmaf(v, scale[d], shift[d]) * mask[bn];
    }
}

extern "C" void kernel_launch(void* const* d_in, const int* in_sizes, int n_in,
                              void* d_out, int out_size) {
    const float* emb   = (const float*)d_in[0];
    const float* dists = (const float*)d_in[1];
    const int*   eidx  = (const int*)d_in[2];
    const float* mask  = (const float*)d_in[3];
    const float* W0 = (const float*)d_in[4];
    const float* b0 = (const float*)d_in[5];
    const float* W1 = (const float*)d_in[6];
    const float* b1 = (const float*)d_in[7];
    const float* W2 = (const float*)d_in[8];
    const float* b2 = (const float*)d_in[9];
    const float* scale = (const float*)d_in[10];
    const float* shift = (const float*)d_in[11];
    float* out = (float*)d_out;

    int smc = 148;
    cudaDeviceGetAttribute(&smc, cudaDevAttrMultiProcessorCount, 0);

    cudaFuncSetAttribute(mpnn_msg_kernel,
                         cudaFuncAttributeMaxDynamicSharedMemorySize, SMEM_BYTES);

    zero_stats_kernel<<<1, 512>>>();
    mpnn_msg_kernel<<<2 * smc, 256, SMEM_BYTES>>>(emb, dists, eidx, mask,
                                                  W0, b0, W1, b1, W2, b2);
    stats_kernel<<<dim3(16, 8), 256>>>(mask);
    norm_kernel<<<4096, 256>>>(mask, scale, shift, out);
}

// round 5
// speedup vs baseline: 2.8252x; 1.7128x over previous
#include <cuda_runtime.h>
#include <cuda_fp16.h>
#include <math.h>
#include <cstdint>

#define B_ 8
#define N_ 8192
#define K_ 32
#define D_ 64

// ---------------- dynamic smem byte offsets ----------------
#define OFF_BFRAG   0          // B frags: 24 combos x (hi 1024B + lo 1024B), lo scaled x256
#define OFF_AGH     49152      // 128 rows x 34 uint (fp16x2 gathered src), 17408B
#define OFF_W0SELF  66560      // [64 i][64 d] f32 (self half of W0, i-major)
#define OFF_SSELF   82944      // 4 x 64 f32 (emb*mask per node)
#define OFF_SELFC   83968      // 4 x 64 f32 (b0 + self-part of layer 0)
#define OFF_SDIST   84992      // 128 f32
#define OFF_SVALID  85504      // 128 f32
#define OFF_SIDX    86016      // 128 i32
#define OFF_WD      86528      // 64 f32 (W0[:,128] dist column)
#define OFF_B1S     86784      // 64 f32
#define OFF_B2S     87040      // 64 f32
#define OFF_FACT    87296      // 4 f32
#define OFF_PART    87312      // 8 warps x 64 f32 partial message sums
#define SMEM_BYTES  89600

// ---------------- device scratch ----------------
__device__ float g_upd[B_ * N_ * D_];
__device__ float g_sum[B_][D_];
__device__ float g_sqs[B_][D_];
__device__ float g_cnt[B_];

// branchless GELU via Abramowitz-Stegun 7.1.26 (abs err ~1.5e-7)
__device__ __forceinline__ float gelu_f(float x) {
    float ax = fabsf(x);
    float y  = ax * 0.7071067811865475f;
    float d  = fmaf(y, 0.3275911f, 1.0f);
    float t;
    asm("rcp.approx.f32 %0, %1;" : "=f"(t) : "f"(d));
    float e;
    asm("ex2.approx.f32 %0, %1;" : "=f"(e) : "f"(y * y * -1.4426950408889634f));
    float p = fmaf(t, 1.061405429f, -1.453152027f);
    p = fmaf(p, t, 1.421413741f);
    p = fmaf(p, t, -0.284496736f);
    p = fmaf(p, t, 0.254829592f);
    p = p * t;
    float erfv = fmaf(-p, e, 1.0f);      // erf(|y|)
    erfv = copysignf(erfv, x);
    return 0.5f * x * (1.0f + erfv);
}

// pack two floats to fp16x2 (first arg -> low half)
__device__ __forceinline__ uint32_t pack_f16x2(float lo, float hi) {
    uint32_t r;
    asm("cvt.rn.f16x2.f32 %0, %1, %2;" : "=r"(r) : "f"(hi), "f"(lo));
    return r;
}

__device__ __forceinline__ void mma_f16(float* d,
                                        uint32_t a0, uint32_t a1, uint32_t a2, uint32_t a3,
                                        uint32_t b0, uint32_t b1) {
    asm volatile(
        "mma.sync.aligned.m16n8k16.row.col.f32.f16.f16.f32 "
        "{%0,%1,%2,%3}, {%4,%5,%6,%7}, {%8,%9}, {%0,%1,%2,%3};"
        : "+f"(d[0]), "+f"(d[1]), "+f"(d[2]), "+f"(d[3])
        : "r"(a0), "r"(a1), "r"(a2), "r"(a3), "r"(b0), "r"(b1));
}

__global__ void __launch_bounds__(256, 2)
mpnn_msg_kernel(const float* __restrict__ emb,
                const float* __restrict__ dists,
                const int*   __restrict__ eidx,
                const float* __restrict__ mask,
                const float* __restrict__ W0, const float* __restrict__ b0,
                const float* __restrict__ W1, const float* __restrict__ b1,
                const float* __restrict__ W2, const float* __restrict__ b2)
{
    extern __shared__ char smb[];
    float* smf = reinterpret_cast<float*>(smb);
    const int tid = threadIdx.x;
    const int w = tid >> 5, lane = tid & 31;
    const int lq = lane >> 2;      // 0..7 (row group)
    const int lr = lane & 3;       // 0..3 (col pair group)

    // ---- one-time staging: B fragments (fp16 hi + lo*256), W0self, wd, biases ----
    for (int c = w; c < 24; c += 8) {
        const int l = c >> 3, t = c & 7;
        const float* W = (l == 0) ? W0 : (l == 1) ? W1 : W2;
        const int stride = (l == 0) ? 129 : 64;
        const int n = t * 8 + lq;
        uint32_t hi[8], lo[8];
#pragma unroll
        for (int j = 0; j < 8; j++) {
            int s = j >> 1, rsel = j & 1;
            int k = 16 * s + 8 * rsel + 2 * lr;
            float x0 = W[n * stride + k];
            float x1 = W[n * stride + k + 1];
            uint32_t h = pack_f16x2(x0, x1);
            __half2 hh = *reinterpret_cast<__half2*>(&h);
            float r0f = x0 - __low2float(hh);
            float r1f = x1 - __high2float(hh);
            hi[j] = h;
            lo[j] = pack_f16x2(r0f * 256.0f, r1f * 256.0f);
        }
        uint4* dh = reinterpret_cast<uint4*>(smb + OFF_BFRAG + c * 2048 + lane * 32);
        uint4* dl = reinterpret_cast<uint4*>(smb + OFF_BFRAG + c * 2048 + 1024 + lane * 32);
        dh[0] = make_uint4(hi[0], hi[1], hi[2], hi[3]);
        dh[1] = make_uint4(hi[4], hi[5], hi[6], hi[7]);
        dl[0] = make_uint4(lo[0], lo[1], lo[2], lo[3]);
        dl[1] = make_uint4(lo[4], lo[5], lo[6], lo[7]);
    }
    for (int p = tid; p < 4096; p += 256) {
        int i = p >> 6, d = p & 63;
        smf[OFF_W0SELF / 4 + p] = W0[d * 129 + 64 + i];
    }
    if (tid < 64) {
        smf[OFF_WD / 4 + tid]  = W0[tid * 129 + 128];
        smf[OFF_B1S / 4 + tid] = b1[tid];
        smf[OFF_B2S / 4 + tid] = b2[tid];
    }
    __syncthreads();

    int* sIdx = reinterpret_cast<int*>(smb + OFF_SIDX);
    const int totalTiles = (B_ * N_) / 4;   // 4 nodes x 32 edges = 128 rows/tile

    for (int tile = blockIdx.x; tile < totalTiles; tile += gridDim.x) {
        const int bn0 = tile << 2;
        const int b   = bn0 >> 13;
        const int n0  = bn0 & (N_ - 1);
        const int bbase = b * N_;

        // ---- phase 1: edge meta + masked self embedding ----
        if (tid < 128) {
            int off = (bbase + n0 + (tid >> 5)) * K_ + (tid & 31);
            int idx = eidx[off];
            smf[OFF_SVALID / 4 + tid] = (idx != -1) ? 1.0f : 0.0f;
            sIdx[tid] = (idx == -1) ? 0 : idx;
            smf[OFF_SDIST / 4 + tid] = dists[off];
        }
        {
            int s = tid >> 6, i = tid & 63;
            int row = bbase + n0 + s;
            smf[OFF_SSELF / 4 + tid] = emb[row * 64 + i] * mask[row];
        }
        __syncthreads();

        // ---- phase 2: gather src rows (fp16x2) + selfC + fact ----
#pragma unroll
        for (int q = 0; q < 8; q++) {
            int p = tid + q * 256;
            int row = p >> 4, c4 = p & 15;
            int gr = bbase + sIdx[row];
            float m = mask[gr];
            float4 v = reinterpret_cast<const float4*>(emb)[(size_t)gr * 16 + c4];
            uint2 pk;
            pk.x = pack_f16x2(v.x * m, v.y * m);
            pk.y = pack_f16x2(v.z * m, v.w * m);
            reinterpret_cast<uint2*>(smb + OFF_AGH)[row * 17 + c4] = pk;
        }
        {
            int s = tid >> 6, d = tid & 63;
            float a = b0[d];
            const float* sv = smf + OFF_SSELF / 4 + s * 64;
            const float* wp = smf + OFF_W0SELF / 4 + d;
#pragma unroll 8
            for (int i = 0; i < 64; i++) a = fmaf(sv[i], wp[i * 64], a);
            smf[OFF_SELFC / 4 + tid] = a;
        }
        if (tid < 4) {
            float c = 0.0f;
            for (int e = 0; e < 32; e++) c += smf[OFF_SVALID / 4 + tid * 32 + e];
            if (c == 0.0f) c = 1.0f;
            smf[OFF_FACT / 4 + tid] = mask[bbase + n0 + tid] / c;
        }
        __syncthreads();

        // ---- build layer-0 A fragments (fp16, single-rounded) ----
        const int r0 = (w << 4) + lq;      // warp's first row + row group
        uint32_t ah[4][4];
        {
            const uint32_t* agh = reinterpret_cast<const uint32_t*>(smb + OFF_AGH);
#pragma unroll
            for (int s = 0; s < 4; s++) {
                int c2 = 8 * s + lr;
                ah[s][0] = agh[r0 * 34 + c2];
                ah[s][1] = agh[(r0 + 8) * 34 + c2];
                ah[s][2] = agh[r0 * 34 + c2 + 4];
                ah[s][3] = agh[(r0 + 8) * 34 + c2 + 4];
            }
        }

        // ---- 3 layers: 2-pass fp16 MMA + register epilogue ----
#pragma unroll
        for (int l = 0; l < 3; l++) {
            float dacc[8][4];
#pragma unroll
            for (int t = 0; t < 8; t++)
#pragma unroll
                for (int j = 0; j < 4; j++) dacc[t][j] = 0.0f;

#pragma unroll
            for (int t = 0; t < 8; t++) {
                const char* base = smb + OFF_BFRAG + (l * 8 + t) * 2048;
                const uint4* bph = reinterpret_cast<const uint4*>(base + lane * 32);
                uint4 h0 = bph[0], h1 = bph[1];
                mma_f16(dacc[t], ah[0][0], ah[0][1], ah[0][2], ah[0][3], h0.x, h0.y);
                mma_f16(dacc[t], ah[1][0], ah[1][1], ah[1][2], ah[1][3], h0.z, h0.w);
                mma_f16(dacc[t], ah[2][0], ah[2][1], ah[2][2], ah[2][3], h1.x, h1.y);
                mma_f16(dacc[t], ah[3][0], ah[3][1], ah[3][2], ah[3][3], h1.z, h1.w);
                const uint4* bpl = reinterpret_cast<const uint4*>(base + 1024 + lane * 32);
                uint4 L0 = bpl[0], L1 = bpl[1];
                float tmp[4] = {0.0f, 0.0f, 0.0f, 0.0f};
                mma_f16(tmp, ah[0][0], ah[0][1], ah[0][2], ah[0][3], L0.x, L0.y);
                mma_f16(tmp, ah[1][0], ah[1][1], ah[1][2], ah[1][3], L0.z, L0.w);
                mma_f16(tmp, ah[2][0], ah[2][1], ah[2][2], ah[2][3], L1.x, L1.y);
                mma_f16(tmp, ah[3][0], ah[3][1], ah[3][2], ah[3][3], L1.z, L1.w);
#pragma unroll
                for (int j = 0; j < 4; j++)
                    dacc[t][j] = fmaf(tmp[j], 0.00390625f, dacc[t][j]);   // 2^-8
            }

            if (l < 2) {
                const int node = w >> 1;
                float dr0 = 0.0f, dr1 = 0.0f;
                if (l == 0) {
                    dr0 = smf[OFF_SDIST / 4 + r0];
                    dr1 = smf[OFF_SDIST / 4 + r0 + 8];
                }
#pragma unroll
                for (int s = 0; s < 4; s++) {
                    float g[8];
#pragma unroll
                    for (int half = 0; half < 2; half++) {
                        const int t = 2 * s + half;
                        const int c0 = 8 * t + 2 * lr;
                        if (l == 0) {
                            float sc0 = smf[OFF_SELFC / 4 + node * 64 + c0];
                            float sc1 = smf[OFF_SELFC / 4 + node * 64 + c0 + 1];
                            float wd0 = smf[OFF_WD / 4 + c0];
                            float wd1 = smf[OFF_WD / 4 + c0 + 1];
                            g[4 * half + 0] = gelu_f(dacc[t][0] + sc0 + dr0 * wd0);
                            g[4 * half + 1] = gelu_f(dacc[t][1] + sc1 + dr0 * wd1);
                            g[4 * half + 2] = gelu_f(dacc[t][2] + sc0 + dr1 * wd0);
                            g[4 * half + 3] = gelu_f(dacc[t][3] + sc1 + dr1 * wd1);
                        } else {
                            float a0 = smf[OFF_B1S / 4 + c0];
                            float a1 = smf[OFF_B1S / 4 + c0 + 1];
                            g[4 * half + 0] = gelu_f(dacc[t][0] + a0);
                            g[4 * half + 1] = gelu_f(dacc[t][1] + a1);
                            g[4 * half + 2] = gelu_f(dacc[t][2] + a0);
                            g[4 * half + 3] = gelu_f(dacc[t][3] + a1);
                        }
                    }
                    ah[s][0] = pack_f16x2(g[0], g[1]);
                    ah[s][1] = pack_f16x2(g[2], g[3]);
                    ah[s][2] = pack_f16x2(g[4], g[5]);
                    ah[s][3] = pack_f16x2(g[6], g[7]);
                }
            } else {
                // layer 2: bias + gelu + valid mask, warp-shuffle reduce over rows
                float v0 = smf[OFF_SVALID / 4 + r0];
                float v1 = smf[OFF_SVALID / 4 + r0 + 8];
                float sc[16];
#pragma unroll
                for (int t = 0; t < 8; t++) {
                    const int c0 = 8 * t + 2 * lr;
                    float bb0 = smf[OFF_B2S / 4 + c0];
                    float bb1 = smf[OFF_B2S / 4 + c0 + 1];
                    sc[2 * t]     = gelu_f(dacc[t][0] + bb0) * v0 + gelu_f(dacc[t][2] + bb0) * v1;
                    sc[2 * t + 1] = gelu_f(dacc[t][1] + bb1) * v0 + gelu_f(dacc[t][3] + bb1) * v1;
                }
#pragma unroll
                for (int off = 4; off <= 16; off <<= 1)
#pragma unroll
                    for (int i = 0; i < 16; i++)
                        sc[i] += __shfl_xor_sync(0xFFFFFFFFu, sc[i], off);
                if (lane < 4) {
#pragma unroll
                    for (int t = 0; t < 8; t++) {
                        smf[OFF_PART / 4 + w * 64 + 8 * t + 2 * lane]     = sc[2 * t];
                        smf[OFF_PART / 4 + w * 64 + 8 * t + 2 * lane + 1] = sc[2 * t + 1];
                    }
                }
            }
        }
        __syncthreads();

        // ---- combine 2 warp-partials per node + write upd ----
        {
            int s = tid >> 6, d = tid & 63;
            float msg = smf[OFF_PART / 4 + (2 * s) * 64 + d] +
                        smf[OFF_PART / 4 + (2 * s + 1) * 64 + d];
            float upd = smf[OFF_SSELF / 4 + s * 64 + d] + msg * smf[OFF_FACT / 4 + s];
            g_upd[(size_t)(bbase + n0 + s) * 64 + d] = upd;
        }
        __syncthreads();
    }
}

// ---------------- stats / norm ----------------
__global__ void zero_stats_kernel() {
    int t = threadIdx.x;
    if (t < B_ * D_) {
        reinterpret_cast<float*>(g_sum)[t] = 0.0f;
        reinterpret_cast<float*>(g_sqs)[t] = 0.0f;
    }
    if (t < B_) g_cnt[t] = 0.0f;
}

__global__ void __launch_bounds__(256)
stats_kernel(const float* __restrict__ mask) {
    __shared__ float sh[512];
    const int b = blockIdx.y;
    const int chunk = blockIdx.x;
    const int tid = threadIdx.x;
    const int d = tid & 63, ro = tid >> 6;
    float s1 = 0.0f, s2 = 0.0f;
    const int base = (b * N_ + chunk * 512) * 64;
    for (int q = 0; q < 128; q++) {
        float v = g_upd[base + (q * 4 + ro) * 64 + d];
        s1 += v;
        s2 = fmaf(v, v, s2);
    }
    sh[tid] = s1;
    sh[256 + tid] = s2;
    __syncthreads();
    if (tid < 64) {
        float a = sh[tid] + sh[tid + 64] + sh[tid + 128] + sh[tid + 192];
        float c = sh[256 + tid] + sh[256 + tid + 64] + sh[256 + tid + 128] + sh[256 + tid + 192];
        atomicAdd(&g_sum[b][tid], a);
        atomicAdd(&g_sqs[b][tid], c);
    }
    __syncthreads();
    float mc = mask[b * N_ + chunk * 512 + tid] + mask[b * N_ + chunk * 512 + 256 + tid];
    sh[tid] = mc;
    __syncthreads();
    for (int st = 128; st >= 1; st >>= 1) {
        if (tid < st) sh[tid] += sh[tid + st];
        __syncthreads();
    }
    if (tid == 0) atomicAdd(&g_cnt[b], sh[0]);
}

__global__ void __launch_bounds__(256)
norm_kernel(const float* __restrict__ mask,
            const float* __restrict__ scale,
            const float* __restrict__ shift,
            float* __restrict__ out) {
    int t = blockIdx.x * 256 + threadIdx.x;
    for (int e = t; e < B_ * N_ * D_; e += gridDim.x * 256) {
        int d  = e & 63;
        int bn = e >> 6;
        int b  = bn >> 13;
        float cnt = g_cnt[b];
        if (cnt == 0.0f) cnt = 1.0f;
        float s1 = g_sum[b][d], s2 = g_sqs[b][d];
        float mean = s1 / cnt;
        float var  = (s2 - 2.0f * mean * s1 + (float)N_ * mean * mean) / cnt;
        float rstd = rsqrtf(var + 1e-5f);
        float v = (g_upd[e] - mean) * rstd;
        out[e] = fmaf(v, scale[d], shift[d]) * mask[bn];
    }
}

extern "C" void kernel_launch(void* const* d_in, const int* in_sizes, int n_in,
                              void* d_out, int out_size) {
    const float* emb   = (const float*)d_in[0];
    const float* dists = (const float*)d_in[1];
    const int*   eidx  = (const int*)d_in[2];
    const float* mask  = (const float*)d_in[3];
    const float* W0 = (const float*)d_in[4];
    const float* b0 = (const float*)d_in[5];
    const float* W1 = (const float*)d_in[6];
    const float* b1 = (const float*)d_in[7];
    const float* W2 = (const float*)d_in[8];
    const float* b2 = (const float*)d_in[9];
    const float* scale = (const float*)d_in[10];
    const float* shift = (const float*)d_in[11];
    float* out = (float*)d_out;

    int smc = 148;
    cudaDeviceGetAttribute(&smc, cudaDevAttrMultiProcessorCount, 0);

    cudaFuncSetAttribute(mpnn_msg_kernel,
                         cudaFuncAttributeMaxDynamicSharedMemorySize, SMEM_BYTES);

    zero_stats_kernel<<<1, 512>>>();
    mpnn_msg_kernel<<<2 * smc, 256, SMEM_BYTES>>>(emb, dists, eidx, mask,
                                                  W0, b0, W1, b1, W2, b2);
    stats_kernel<<<dim3(16, 8), 256>>>(mask);
    norm_kernel<<<4096, 256>>>(mask, scale, shift, out);
}

// round 7
// speedup vs baseline: 3.3419x; 1.1829x over previous
#include <cuda_runtime.h>
#include <cuda_fp16.h>
#include <math.h>
#include <cstdint>

#define B_ 8
#define N_ 8192
#define K_ 32
#define D_ 64

// ---------------- dynamic smem byte offsets ----------------
#define OFF_BFRAG   0          // B frags: 24 combos x (hi 1024B + lo 1024B), lo scaled x256; W1,W2 pre-halved
#define OFF_AGH     49152      // 128 rows x 34 uint (fp16x2 gathered src), 17408B
#define OFF_W0SELF  66560      // [64 i][64 d] f32 (self half of W0, i-major)
#define OFF_SSELF   82944      // 4 x 64 f32 (emb*mask per node)
#define OFF_SELFC   83968      // 4 x 64 f32 (b0 + self-part of layer 0)
#define OFF_SDIST   84992      // 128 f32
#define OFF_SVALID  85504      // 128 f32
#define OFF_SIDX    86016      // 128 i32
#define OFF_WD      86528      // 64 f32 (W0[:,128] dist column)
#define OFF_B1S     86784      // 64 f32
#define OFF_B2S     87040      // 64 f32
#define OFF_FACT    87296      // 4 f32 (mask*0.5/n_valid)
#define OFF_PART    87312      // 8 warps x 64 f32 partial message sums
#define OFF_UPD     89360      // 512 f32: upd staging (u at [tid], u^2 at [256+tid])
#define OFF_SACC    93456      // 8 b x 64 d x 2 f32 block-local stats accumulators
#define SMEM_BYTES  97664

// ---------------- device scratch ----------------
__device__ float g_upd[B_ * N_ * D_];
__device__ float g_sum[B_][D_];
__device__ float g_sqs[B_][D_];
__device__ float g_cnt[B_];

// returns 2*gelu(x) = x + |x|*erf(|x|/sqrt(2)); A&S 7.1.25 3-term, |eps|<=2.5e-5
__device__ __forceinline__ float gelu2x(float x) {
    float ax = fabsf(x);
    float y  = 0.7071067811865475f * ax;
    float d  = fmaf(y, 0.47047f, 1.0f);
    float t;
    asm("rcp.approx.f32 %0, %1;" : "=f"(t) : "f"(d));
    float q = 0.84932180f * ax;              // q*q = 0.72134752*x^2 = y^2*log2(e)
    float e;
    asm("ex2.approx.f32 %0, %1;" : "=f"(e) : "f"(-q * q));
    float p = fmaf(t, 0.7478556f, -0.0958798f);
    p = fmaf(p, t, 0.3480242f);
    p = p * t;
    float E = fmaf(-p, e, 1.0f);             // erf(y)
    return fmaf(ax, E, x);                   // x + |x|*erf = 2*gelu(x)
}

// pack two floats to fp16x2 (first arg -> low half)
__device__ __forceinline__ uint32_t pack_f16x2(float lo, float hi) {
    uint32_t r;
    asm("cvt.rn.f16x2.f32 %0, %1, %2;" : "=r"(r) : "f"(hi), "f"(lo));
    return r;
}

__device__ __forceinline__ void mma_f16(float* d,
                                        uint32_t a0, uint32_t a1, uint32_t a2, uint32_t a3,
                                        uint32_t b0, uint32_t b1) {
    asm volatile(
        "mma.sync.aligned.m16n8k16.row.col.f32.f16.f16.f32 "
        "{%0,%1,%2,%3}, {%4,%5,%6,%7}, {%8,%9}, {%0,%1,%2,%3};"
        : "+f"(d[0]), "+f"(d[1]), "+f"(d[2]), "+f"(d[3])
        : "r"(a0), "r"(a1), "r"(a2), "r"(a3), "r"(b0), "r"(b1));
}

__global__ void __launch_bounds__(256, 2)
mpnn_msg_kernel(const float* __restrict__ emb,
                const float* __restrict__ dists,
                const int*   __restrict__ eidx,
                const float* __restrict__ mask,
                const float* __restrict__ W0, const float* __restrict__ b0,
                const float* __restrict__ W1, const float* __restrict__ b1,
                const float* __restrict__ W2, const float* __restrict__ b2)
{
    extern __shared__ char smb[];
    float* smf = reinterpret_cast<float*>(smb);
    const int tid = threadIdx.x;
    const int w = tid >> 5, lane = tid & 31;
    const int lq = lane >> 2;      // 0..7 (row group)
    const int lr = lane & 3;       // 0..3 (col pair group)

    // ---- one-time staging ----
    // B fragments; layers 1,2 pre-scaled by 0.5 (gelu2x emits 2*gelu)
    for (int c = w; c < 24; c += 8) {
        const int l = c >> 3, t = c & 7;
        const float* W = (l == 0) ? W0 : (l == 1) ? W1 : W2;
        const int stride = (l == 0) ? 129 : 64;
        const float wsc = (l == 0) ? 1.0f : 0.5f;
        const int n = t * 8 + lq;
        uint32_t hi[8], lo[8];
#pragma unroll
        for (int j = 0; j < 8; j++) {
            int s = j >> 1, rsel = j & 1;
            int k = 16 * s + 8 * rsel + 2 * lr;
            float x0 = W[n * stride + k] * wsc;
            float x1 = W[n * stride + k + 1] * wsc;
            uint32_t h = pack_f16x2(x0, x1);
            __half2 hh = *reinterpret_cast<__half2*>(&h);
            float r0f = x0 - __low2float(hh);
            float r1f = x1 - __high2float(hh);
            hi[j] = h;
            lo[j] = pack_f16x2(r0f * 256.0f, r1f * 256.0f);
        }
        uint4* dh = reinterpret_cast<uint4*>(smb + OFF_BFRAG + c * 2048 + lane * 32);
        uint4* dl = reinterpret_cast<uint4*>(smb + OFF_BFRAG + c * 2048 + 1024 + lane * 32);
        dh[0] = make_uint4(hi[0], hi[1], hi[2], hi[3]);
        dh[1] = make_uint4(hi[4], hi[5], hi[6], hi[7]);
        dl[0] = make_uint4(lo[0], lo[1], lo[2], lo[3]);
        dl[1] = make_uint4(lo[4], lo[5], lo[6], lo[7]);
    }
    for (int p = tid; p < 4096; p += 256) {
        int i = p >> 6, d = p & 63;
        smf[OFF_W0SELF / 4 + p] = W0[d * 129 + 64 + i];
    }
    if (tid < 64) {
        smf[OFF_WD / 4 + tid]  = W0[tid * 129 + 128];
        smf[OFF_B1S / 4 + tid] = b1[tid];
        smf[OFF_B2S / 4 + tid] = b2[tid];
    }
    // zero block-local stats accumulators
    for (int p = tid; p < 1024; p += 256) smf[OFF_SACC / 4 + p] = 0.0f;
    __syncthreads();

    int* sIdx = reinterpret_cast<int*>(smb + OFF_SIDX);
    const int totalTiles = (B_ * N_) / 4;   // 4 nodes x 32 edges = 128 rows/tile

    for (int tile = blockIdx.x; tile < totalTiles; tile += gridDim.x) {
        const int bn0 = tile << 2;
        const int b   = bn0 >> 13;
        const int n0  = bn0 & (N_ - 1);
        const int bbase = b * N_;

        // ---- phase 1: edge meta + masked self embedding ----
        if (tid < 128) {
            int off = (bbase + n0 + (tid >> 5)) * K_ + (tid & 31);
            int idx = eidx[off];
            smf[OFF_SVALID / 4 + tid] = (idx != -1) ? 1.0f : 0.0f;
            sIdx[tid] = (idx == -1) ? 0 : idx;
            smf[OFF_SDIST / 4 + tid] = dists[off];
        }
        {
            int s = tid >> 6, i = tid & 63;
            int row = bbase + n0 + s;
            smf[OFF_SSELF / 4 + tid] = emb[row * 64 + i] * mask[row];
        }
        __syncthreads();

        // ---- phase 2: gather src rows (fp16x2) + selfC + fact ----
#pragma unroll
        for (int q = 0; q < 8; q++) {
            int p = tid + q * 256;
            int row = p >> 4, c4 = p & 15;
            int gr = bbase + sIdx[row];
            float m = mask[gr];
            float4 v = reinterpret_cast<const float4*>(emb)[(size_t)gr * 16 + c4];
            uint2 pk;
            pk.x = pack_f16x2(v.x * m, v.y * m);
            pk.y = pack_f16x2(v.z * m, v.w * m);
            reinterpret_cast<uint2*>(smb + OFF_AGH)[row * 17 + c4] = pk;
        }
        {
            int s = tid >> 6, d = tid & 63;
            float a = b0[d];
            const float* sv = smf + OFF_SSELF / 4 + s * 64;
            const float* wp = smf + OFF_W0SELF / 4 + d;
#pragma unroll 8
            for (int i = 0; i < 64; i++) a = fmaf(sv[i], wp[i * 64], a);
            smf[OFF_SELFC / 4 + tid] = a;
        }
        if (tid < 4) {
            float c = 0.0f;
            for (int e = 0; e < 32; e++) c += smf[OFF_SVALID / 4 + tid * 32 + e];
            if (c == 0.0f) c = 1.0f;
            smf[OFF_FACT / 4 + tid] = mask[bbase + n0 + tid] * 0.5f / c;
        }
        __syncthreads();

        // ---- build layer-0 A fragments (fp16, single-rounded) ----
        const int r0 = (w << 4) + lq;      // warp's first row + row group
        uint32_t ah[4][4];
        {
            const uint32_t* agh = reinterpret_cast<const uint32_t*>(smb + OFF_AGH);
#pragma unroll
            for (int s = 0; s < 4; s++) {
                int c2 = 8 * s + lr;
                ah[s][0] = agh[r0 * 34 + c2];
                ah[s][1] = agh[(r0 + 8) * 34 + c2];
                ah[s][2] = agh[r0 * 34 + c2 + 4];
                ah[s][3] = agh[(r0 + 8) * 34 + c2 + 4];
            }
        }

        // ---- 3 layers: 2-pass fp16 MMA + register epilogue ----
#pragma unroll
        for (int l = 0; l < 3; l++) {
            float dacc[8][4];
            // accumulator init carries bias / selfC+dist terms
            if (l == 0) {
                const int node = w >> 1;
                float dr0 = smf[OFF_SDIST / 4 + r0];
                float dr1 = smf[OFF_SDIST / 4 + r0 + 8];
#pragma unroll
                for (int t = 0; t < 8; t++) {
                    const int c0 = 8 * t + 2 * lr;
                    float sc0 = smf[OFF_SELFC / 4 + node * 64 + c0];
                    float sc1 = smf[OFF_SELFC / 4 + node * 64 + c0 + 1];
                    float wd0 = smf[OFF_WD / 4 + c0];
                    float wd1 = smf[OFF_WD / 4 + c0 + 1];
                    dacc[t][0] = fmaf(dr0, wd0, sc0);
                    dacc[t][1] = fmaf(dr0, wd1, sc1);
                    dacc[t][2] = fmaf(dr1, wd0, sc0);
                    dacc[t][3] = fmaf(dr1, wd1, sc1);
                }
            } else {
                const float* bb = smf + ((l == 1) ? OFF_B1S : OFF_B2S) / 4;
#pragma unroll
                for (int t = 0; t < 8; t++) {
                    const int c0 = 8 * t + 2 * lr;
                    float b0v = bb[c0], b1v = bb[c0 + 1];
                    dacc[t][0] = b0v; dacc[t][2] = b0v;
                    dacc[t][1] = b1v; dacc[t][3] = b1v;
                }
            }

#pragma unroll
            for (int t = 0; t < 8; t++) {
                const char* base = smb + OFF_BFRAG + (l * 8 + t) * 2048;
                const uint4* bph = reinterpret_cast<const uint4*>(base + lane * 32);
                uint4 h0 = bph[0], h1 = bph[1];
                mma_f16(dacc[t], ah[0][0], ah[0][1], ah[0][2], ah[0][3], h0.x, h0.y);
                mma_f16(dacc[t], ah[1][0], ah[1][1], ah[1][2], ah[1][3], h0.z, h0.w);
                mma_f16(dacc[t], ah[2][0], ah[2][1], ah[2][2], ah[2][3], h1.x, h1.y);
                mma_f16(dacc[t], ah[3][0], ah[3][1], ah[3][2], ah[3][3], h1.z, h1.w);
                const uint4* bpl = reinterpret_cast<const uint4*>(base + 1024 + lane * 32);
                uint4 L0 = bpl[0], L1 = bpl[1];
                float tmp[4] = {0.0f, 0.0f, 0.0f, 0.0f};
                mma_f16(tmp, ah[0][0], ah[0][1], ah[0][2], ah[0][3], L0.x, L0.y);
                mma_f16(tmp, ah[1][0], ah[1][1], ah[1][2], ah[1][3], L0.z, L0.w);
                mma_f16(tmp, ah[2][0], ah[2][1], ah[2][2], ah[2][3], L1.x, L1.y);
                mma_f16(tmp, ah[3][0], ah[3][1], ah[3][2], ah[3][3], L1.z, L1.w);
#pragma unroll
                for (int j = 0; j < 4; j++)
                    dacc[t][j] = fmaf(tmp[j], 0.00390625f, dacc[t][j]);   // 2^-8
            }

            if (l < 2) {
#pragma unroll
                for (int s = 0; s < 4; s++) {
                    float g[8];
#pragma unroll
                    for (int half = 0; half < 2; half++) {
                        const int t = 2 * s + half;
                        g[4 * half + 0] = gelu2x(dacc[t][0]);
                        g[4 * half + 1] = gelu2x(dacc[t][1]);
                        g[4 * half + 2] = gelu2x(dacc[t][2]);
                        g[4 * half + 3] = gelu2x(dacc[t][3]);
                    }
                    ah[s][0] = pack_f16x2(g[0], g[1]);
                    ah[s][1] = pack_f16x2(g[2], g[3]);
                    ah[s][2] = pack_f16x2(g[4], g[5]);
                    ah[s][3] = pack_f16x2(g[6], g[7]);
                }
            } else {
                // layer 2: gelu2x + valid mask, warp-shuffle reduce over rows
                float v0 = smf[OFF_SVALID / 4 + r0];
                float v1 = smf[OFF_SVALID / 4 + r0 + 8];
                float sc[16];
#pragma unroll
                for (int t = 0; t < 8; t++) {
                    sc[2 * t]     = gelu2x(dacc[t][0]) * v0 + gelu2x(dacc[t][2]) * v1;
                    sc[2 * t + 1] = gelu2x(dacc[t][1]) * v0 + gelu2x(dacc[t][3]) * v1;
                }
#pragma unroll
                for (int off = 4; off <= 16; off <<= 1)
#pragma unroll
                    for (int i = 0; i < 16; i++)
                        sc[i] += __shfl_xor_sync(0xFFFFFFFFu, sc[i], off);
                if (lane < 4) {
#pragma unroll
                    for (int t = 0; t < 8; t++) {
                        smf[OFF_PART / 4 + w * 64 + 8 * t + 2 * lane]     = sc[2 * t];
                        smf[OFF_PART / 4 + w * 64 + 8 * t + 2 * lane + 1] = sc[2 * t + 1];
                    }
                }
            }
        }
        __syncthreads();

        // ---- combine 2 warp-partials per node, write upd, stage stats ----
        {
            int s = tid >> 6, d = tid & 63;
            float msg = smf[OFF_PART / 4 + (2 * s) * 64 + d] +
                        smf[OFF_PART / 4 + (2 * s + 1) * 64 + d];
            float upd = smf[OFF_SSELF / 4 + s * 64 + d] + msg * smf[OFF_FACT / 4 + s];
            g_upd[(size_t)(bbase + n0 + s) * 64 + d] = upd;
            smf[OFF_UPD / 4 + tid]       = upd;
            smf[OFF_UPD / 4 + 256 + tid] = upd * upd;
        }
        __syncthreads();
        // owner threads fold 4 nodes into block-local per-(b,d) stats
        if (tid < 64) {
            const float* st = smf + OFF_UPD / 4;
            float s1 = st[tid] + st[64 + tid] + st[128 + tid] + st[192 + tid];
            float s2 = st[256 + tid] + st[320 + tid] + st[384 + tid] + st[448 + tid];
            smf[OFF_SACC / 4 + b * 128 + tid]      += s1;
            smf[OFF_SACC / 4 + b * 128 + 64 + tid] += s2;
        }
    }

    // ---- flush block-local stats (all 8 batches x 64 ch x {sum,sqs}) ----
    __syncthreads();
    for (int p = tid; p < 1024; p += 256) {
        int bb2 = p >> 7;            // batch
        int rem = p & 127;           // 0..63 sum, 64..127 sqs
        float v = smf[OFF_SACC / 4 + p];
        if (rem < 64) atomicAdd(&g_sum[bb2][rem], v);
        else          atomicAdd(&g_sqs[bb2][rem - 64], v);
    }
}

// ---------------- init: zero stats + mask counts ----------------
__global__ void __launch_bounds__(256)
init_stats_kernel(const float* __restrict__ mask) {
    __shared__ float sh[256];
    const int b = blockIdx.x;
    const int tid = threadIdx.x;
    if (tid < 64) {
        g_sum[b][tid] = 0.0f;
        g_sqs[b][tid] = 0.0f;
    }
    float c = 0.0f;
    for (int i = tid; i < N_; i += 256) c += mask[b * N_ + i];
    sh[tid] = c;
    __syncthreads();
    for (int st = 128; st >= 1; st >>= 1) {
        if (tid < st) sh[tid] += sh[tid + st];
        __syncthreads();
    }
    if (tid == 0) {
        float cc = sh[0];
        g_cnt[b] = (cc == 0.0f) ? 1.0f : cc;
    }
}

__global__ void __launch_bounds__(256)
norm_kernel(const float* __restrict__ mask,
            const float* __restrict__ scale,
            const float* __restrict__ shift,
            float* __restrict__ out) {
    int t = blockIdx.x * 256 + threadIdx.x;        // 1M threads, 1 float4 each
    int bn = t >> 4;
    int b  = bn >> 13;
    int d0 = (t & 15) << 2;
    float cnt = g_cnt[b];
    float4 s1 = *reinterpret_cast<const float4*>(&g_sum[b][d0]);
    float4 s2 = *reinterpret_cast<const float4*>(&g_sqs[b][d0]);
    float4 u  = reinterpret_cast<const float4*>(g_upd)[t];
    float m   = mask[bn];
    float rc  = 1.0f / cnt;
    float4 o;
    {
        float mean = s1.x * rc;
        float var  = (s2.x - 2.0f * mean * s1.x + (float)N_ * mean * mean) * rc;
        o.x = fmaf((u.x - mean) * rsqrtf(var + 1e-5f), scale[d0 + 0], shift[d0 + 0]) * m;
    }
    {
        float mean = s1.y * rc;
        float var  = (s2.y - 2.0f * mean * s1.y + (float)N_ * mean * mean) * rc;
        o.y = fmaf((u.y - mean) * rsqrtf(var + 1e-5f), scale[d0 + 1], shift[d0 + 1]) * m;
    }
    {
        float mean = s1.z * rc;
        float var  = (s2.z - 2.0f * mean * s1.z + (float)N_ * mean * mean) * rc;
        o.z = fmaf((u.z - mean) * rsqrtf(var + 1e-5f), scale[d0 + 2], shift[d0 + 2]) * m;
    }
    {
        float mean = s1.w * rc;
        float var  = (s2.w - 2.0f * mean * s1.w + (float)N_ * mean * mean) * rc;
        o.w = fmaf((u.w - mean) * rsqrtf(var + 1e-5f), scale[d0 + 3], shift[d0 + 3]) * m;
    }
    reinterpret_cast<float4*>(out)[t] = o;
}

extern "C" void kernel_launch(void* const* d_in, const int* in_sizes, int n_in,
                              void* d_out, int out_size) {
    const float* emb   = (const float*)d_in[0];
    const float* dists = (const float*)d_in[1];
    const int*   eidx  = (const int*)d_in[2];
    const float* mask  = (const float*)d_in[3];
    const float* W0 = (const float*)d_in[4];
    const float* b0 = (const float*)d_in[5];
    const float* W1 = (const float*)d_in[6];
    const float* b1 = (const float*)d_in[7];
    const float* W2 = (const float*)d_in[8];
    const float* b2 = (const float*)d_in[9];
    const float* scale = (const float*)d_in[10];
    const float* shift = (const float*)d_in[11];
    float* out = (float*)d_out;

    int smc = 148;
    cudaDeviceGetAttribute(&smc, cudaDevAttrMultiProcessorCount, 0);

    cudaFuncSetAttribute(mpnn_msg_kernel,
                         cudaFuncAttributeMaxDynamicSharedMemorySize, SMEM_BYTES);

    init_stats_kernel<<<B_, 256>>>(mask);
    mpnn_msg_kernel<<<2 * smc, 256, SMEM_BYTES>>>(emb, dists, eidx, mask,
                                                  W0, b0, W1, b1, W2, b2);
    norm_kernel<<<(B_ * N_ * D_ / 4 + 255) / 256, 256>>>(mask, scale, shift, out);
}

// round 8
// speedup vs baseline: 3.6066x; 1.0792x over previous
#include <cuda_runtime.h>
#include <cuda_fp16.h>
#include <math.h>
#include <cstdint>

#define B_ 8
#define N_ 8192
#define K_ 32
#define D_ 64

typedef unsigned long long ull;

// ---------------- dynamic smem byte offsets ----------------
#define OFF_BFRAG   0          // B frags: 24 combos x (hi 1024B + lo 1024B), lo scaled x256; W1,W2 pre-halved
#define OFF_AGH     49152      // 128 rows x 34 uint (fp16x2 gathered src), 17408B
#define OFF_W0SELF  66560      // [64 i][64 d] f32 (self half of W0, i-major)
#define OFF_SSELF   82944      // 4 x 64 f32 (emb*mask per node)
#define OFF_SELFC   83968      // 4 x 64 f32 (b0 + self-part of layer 0)
#define OFF_SDIST   84992      // 128 f32
#define OFF_SVALID  85504      // 128 f32
#define OFF_SIDX    86016      // 128 i32
#define OFF_WD      86528      // 64 f32 (W0[:,128] dist column)
#define OFF_B1S     86784      // 64 f32
#define OFF_B2S     87040      // 64 f32
#define OFF_FACT    87296      // 4 f32 (mask*0.5/n_valid)
#define OFF_PART    87312      // 8 warps x 64 f32 partial message sums
#define OFF_UPD     89360      // 512 f32: upd staging (u at [tid], u^2 at [256+tid])
#define OFF_SACC    93456      // 8 b x 64 d x 2 f32 block-local stats accumulators
#define SMEM_BYTES  97664

// ---------------- device scratch ----------------
__device__ float g_upd[B_ * N_ * D_];
__device__ float g_sum[B_][D_];
__device__ float g_sqs[B_][D_];
__device__ float g_cnt[B_];

// ---------------- packed f32x2 helpers ----------------
__device__ __forceinline__ ull pk2(float a, float b) {
    ull r; asm("mov.b64 %0, {%1, %2};" : "=l"(r) : "f"(a), "f"(b)); return r;
}
__device__ __forceinline__ void upk2(ull v, float& a, float& b) {
    asm("mov.b64 {%0, %1}, %2;" : "=f"(a), "=f"(b) : "l"(v));
}
__device__ __forceinline__ ull f2mul(ull a, ull b) {
    ull r; asm("mul.rn.f32x2 %0, %1, %2;" : "=l"(r) : "l"(a), "l"(b)); return r;
}
__device__ __forceinline__ ull f2add(ull a, ull b) {
    ull r; asm("add.rn.f32x2 %0, %1, %2;" : "=l"(r) : "l"(a), "l"(b)); return r;
}
__device__ __forceinline__ ull f2fma(ull a, ull b, ull c) {
    ull r; asm("fma.rn.f32x2 %0, %1, %2, %3;" : "=l"(r) : "l"(a), "l"(b), "l"(c)); return r;
}

// packed gelu constants (built once per thread)
struct GP { ull A, ONE, Q2, C3, C2, C1; };

// packed 2*gelu(x) per lane: x + |x|*erf(|x|/sqrt2), A&S 7.1.25 3-term
__device__ __forceinline__ ull gelu2x_pk(ull x, const GP& K) {
    ull ax = x & 0x7FFFFFFF7FFFFFFFull;
    ull d  = f2fma(ax, K.A, K.ONE);          // 1 + 0.3326724*|x|
    ull xx = f2mul(x, x);
    ull ea = f2mul(xx, K.Q2);                // -0.72134752*x^2  (= -y^2*log2e)
    float d0, d1; upk2(d, d0, d1);
    float t0, t1;
    asm("rcp.approx.f32 %0, %1;" : "=f"(t0) : "f"(d0));
    asm("rcp.approx.f32 %0, %1;" : "=f"(t1) : "f"(d1));
    float e0, e1; upk2(ea, e0, e1);
    asm("ex2.approx.f32 %0, %1;" : "=f"(e0) : "f"(e0));
    asm("ex2.approx.f32 %0, %1;" : "=f"(e1) : "f"(e1));
    ull t = pk2(t0, t1);
    ull p = f2fma(t, K.C3, K.C2);
    p = f2fma(p, t, K.C1);
    p = f2mul(p, t);
    ull e = pk2(e0, e1);
    ull pe = f2mul(p, e);
    ull nax = ax ^ 0x8000000080000000ull;    // -|x|
    ull s = f2add(x, ax);                    // x + |x|
    return f2fma(pe, nax, s);                // x + |x|*(1 - p*e)
}

// pack two floats to fp16x2 (first arg -> low half)
__device__ __forceinline__ uint32_t pack_f16x2(float lo, float hi) {
    uint32_t r;
    asm("cvt.rn.f16x2.f32 %0, %1, %2;" : "=r"(r) : "f"(hi), "f"(lo));
    return r;
}
// packed f32x2 -> fp16x2 (low lane -> low half)
__device__ __forceinline__ uint32_t pk_to_f16(ull v) {
    float a, b; upk2(v, a, b);
    return pack_f16x2(a, b);
}

__device__ __forceinline__ void mma_f16(float* d,
                                        uint32_t a0, uint32_t a1, uint32_t a2, uint32_t a3,
                                        uint32_t b0, uint32_t b1) {
    asm volatile(
        "mma.sync.aligned.m16n8k16.row.col.f32.f16.f16.f32 "
        "{%0,%1,%2,%3}, {%4,%5,%6,%7}, {%8,%9}, {%0,%1,%2,%3};"
        : "+f"(d[0]), "+f"(d[1]), "+f"(d[2]), "+f"(d[3])
        : "r"(a0), "r"(a1), "r"(a2), "r"(a3), "r"(b0), "r"(b1));
}

__global__ void __launch_bounds__(256, 2)
mpnn_msg_kernel(const float* __restrict__ emb,
                const float* __restrict__ dists,
                const int*   __restrict__ eidx,
                const float* __restrict__ mask,
                const float* __restrict__ W0, const float* __restrict__ b0,
                const float* __restrict__ W1, const float* __restrict__ b1,
                const float* __restrict__ W2, const float* __restrict__ b2)
{
    extern __shared__ char smb[];
    float* smf = reinterpret_cast<float*>(smb);
    const int tid = threadIdx.x;
    const int w = tid >> 5, lane = tid & 31;
    const int lq = lane >> 2;      // 0..7 (row group)
    const int lr = lane & 3;       // 0..3 (col pair group)

    GP K;
    K.A   = pk2(0.3326724f, 0.3326724f);
    K.ONE = pk2(1.0f, 1.0f);
    K.Q2  = pk2(-0.72134752f, -0.72134752f);
    K.C3  = pk2(0.7478556f, 0.7478556f);
    K.C2  = pk2(-0.0958798f, -0.0958798f);
    K.C1  = pk2(0.3480242f, 0.3480242f);

    // ---- one-time staging ----
    // B fragments; layers 1,2 pre-scaled by 0.5 (gelu2x emits 2*gelu)
    for (int c = w; c < 24; c += 8) {
        const int l = c >> 3, t = c & 7;
        const float* W = (l == 0) ? W0 : (l == 1) ? W1 : W2;
        const int stride = (l == 0) ? 129 : 64;
        const float wsc = (l == 0) ? 1.0f : 0.5f;
        const int n = t * 8 + lq;
        uint32_t hi[8], lo[8];
#pragma unroll
        for (int j = 0; j < 8; j++) {
            int s = j >> 1, rsel = j & 1;
            int k = 16 * s + 8 * rsel + 2 * lr;
            float x0 = W[n * stride + k] * wsc;
            float x1 = W[n * stride + k + 1] * wsc;
            uint32_t h = pack_f16x2(x0, x1);
            __half2 hh = *reinterpret_cast<__half2*>(&h);
            float r0f = x0 - __low2float(hh);
            float r1f = x1 - __high2float(hh);
            hi[j] = h;
            lo[j] = pack_f16x2(r0f * 256.0f, r1f * 256.0f);
        }
        uint4* dh = reinterpret_cast<uint4*>(smb + OFF_BFRAG + c * 2048 + lane * 32);
        uint4* dl = reinterpret_cast<uint4*>(smb + OFF_BFRAG + c * 2048 + 1024 + lane * 32);
        dh[0] = make_uint4(hi[0], hi[1], hi[2], hi[3]);
        dh[1] = make_uint4(hi[4], hi[5], hi[6], hi[7]);
        dl[0] = make_uint4(lo[0], lo[1], lo[2], lo[3]);
        dl[1] = make_uint4(lo[4], lo[5], lo[6], lo[7]);
    }
    for (int p = tid; p < 4096; p += 256) {
        int i = p >> 6, d = p & 63;
        smf[OFF_W0SELF / 4 + p] = W0[d * 129 + 64 + i];
    }
    if (tid < 64) {
        smf[OFF_WD / 4 + tid]  = W0[tid * 129 + 128];
        smf[OFF_B1S / 4 + tid] = b1[tid];
        smf[OFF_B2S / 4 + tid] = b2[tid];
    }
    // zero block-local stats accumulators
    for (int p = tid; p < 1024; p += 256) smf[OFF_SACC / 4 + p] = 0.0f;
    __syncthreads();

    int* sIdx = reinterpret_cast<int*>(smb + OFF_SIDX);
    const int totalTiles = (B_ * N_) / 4;   // 4 nodes x 32 edges = 128 rows/tile

    for (int tile = blockIdx.x; tile < totalTiles; tile += gridDim.x) {
        const int bn0 = tile << 2;
        const int b   = bn0 >> 13;
        const int n0  = bn0 & (N_ - 1);
        const int bbase = b * N_;

        // ---- phase 1: edge meta + masked self embedding ----
        if (tid < 128) {
            int off = (bbase + n0 + (tid >> 5)) * K_ + (tid & 31);
            int idx = eidx[off];
            smf[OFF_SVALID / 4 + tid] = (idx != -1) ? 1.0f : 0.0f;
            sIdx[tid] = (idx == -1) ? 0 : idx;
            smf[OFF_SDIST / 4 + tid] = dists[off];
        }
        {
            int s = tid >> 6, i = tid & 63;
            int row = bbase + n0 + s;
            smf[OFF_SSELF / 4 + tid] = emb[row * 64 + i] * mask[row];
        }
        __syncthreads();

        // ---- phase 2: gather src rows (fp16x2) + selfC + fact ----
#pragma unroll
        for (int q = 0; q < 8; q++) {
            int p = tid + q * 256;
            int row = p >> 4, c4 = p & 15;
            int gr = bbase + sIdx[row];
            float m = mask[gr];
            float4 v = reinterpret_cast<const float4*>(emb)[(size_t)gr * 16 + c4];
            uint2 pk;
            pk.x = pack_f16x2(v.x * m, v.y * m);
            pk.y = pack_f16x2(v.z * m, v.w * m);
            reinterpret_cast<uint2*>(smb + OFF_AGH)[row * 17 + c4] = pk;
        }
        {
            int s = tid >> 6, d = tid & 63;
            float a = b0[d];
            const float* sv = smf + OFF_SSELF / 4 + s * 64;
            const float* wp = smf + OFF_W0SELF / 4 + d;
#pragma unroll 8
            for (int i = 0; i < 64; i++) a = fmaf(sv[i], wp[i * 64], a);
            smf[OFF_SELFC / 4 + tid] = a;
        }
        if (tid < 4) {
            float c = 0.0f;
            for (int e = 0; e < 32; e++) c += smf[OFF_SVALID / 4 + tid * 32 + e];
            if (c == 0.0f) c = 1.0f;
            smf[OFF_FACT / 4 + tid] = mask[bbase + n0 + tid] * 0.5f / c;
        }
        __syncthreads();

        // ---- build layer-0 A fragments (fp16, single-rounded) ----
        const int r0 = (w << 4) + lq;      // warp's first row + row group
        uint32_t ah[4][4];
        {
            const uint32_t* agh = reinterpret_cast<const uint32_t*>(smb + OFF_AGH);
#pragma unroll
            for (int s = 0; s < 4; s++) {
                int c2 = 8 * s + lr;
                ah[s][0] = agh[r0 * 34 + c2];
                ah[s][1] = agh[(r0 + 8) * 34 + c2];
                ah[s][2] = agh[r0 * 34 + c2 + 4];
                ah[s][3] = agh[(r0 + 8) * 34 + c2 + 4];
            }
        }

        // ---- 3 layers: 2-pass fp16 MMA + packed register epilogue ----
#pragma unroll
        for (int l = 0; l < 3; l++) {
            float dacc[8][4];
            // accumulator init carries bias / selfC+dist terms
            if (l == 0) {
                const int node = w >> 1;
                float dr0 = smf[OFF_SDIST / 4 + r0];
                float dr1 = smf[OFF_SDIST / 4 + r0 + 8];
#pragma unroll
                for (int t = 0; t < 8; t++) {
                    const int c0 = 8 * t + 2 * lr;
                    float sc0 = smf[OFF_SELFC / 4 + node * 64 + c0];
                    float sc1 = smf[OFF_SELFC / 4 + node * 64 + c0 + 1];
                    float wd0 = smf[OFF_WD / 4 + c0];
                    float wd1 = smf[OFF_WD / 4 + c0 + 1];
                    dacc[t][0] = fmaf(dr0, wd0, sc0);
                    dacc[t][1] = fmaf(dr0, wd1, sc1);
                    dacc[t][2] = fmaf(dr1, wd0, sc0);
                    dacc[t][3] = fmaf(dr1, wd1, sc1);
                }
            } else {
                const float* bb = smf + ((l == 1) ? OFF_B1S : OFF_B2S) / 4;
#pragma unroll
                for (int t = 0; t < 8; t++) {
                    const int c0 = 8 * t + 2 * lr;
                    float b0v = bb[c0], b1v = bb[c0 + 1];
                    dacc[t][0] = b0v; dacc[t][2] = b0v;
                    dacc[t][1] = b1v; dacc[t][3] = b1v;
                }
            }

#pragma unroll
            for (int t = 0; t < 8; t++) {
                const char* base = smb + OFF_BFRAG + (l * 8 + t) * 2048;
                const uint4* bph = reinterpret_cast<const uint4*>(base + lane * 32);
                uint4 h0 = bph[0], h1 = bph[1];
                mma_f16(dacc[t], ah[0][0], ah[0][1], ah[0][2], ah[0][3], h0.x, h0.y);
                mma_f16(dacc[t], ah[1][0], ah[1][1], ah[1][2], ah[1][3], h0.z, h0.w);
                mma_f16(dacc[t], ah[2][0], ah[2][1], ah[2][2], ah[2][3], h1.x, h1.y);
                mma_f16(dacc[t], ah[3][0], ah[3][1], ah[3][2], ah[3][3], h1.z, h1.w);
                const uint4* bpl = reinterpret_cast<const uint4*>(base + 1024 + lane * 32);
                uint4 L0 = bpl[0], L1 = bpl[1];
                float tmp[4] = {0.0f, 0.0f, 0.0f, 0.0f};
                mma_f16(tmp, ah[0][0], ah[0][1], ah[0][2], ah[0][3], L0.x, L0.y);
                mma_f16(tmp, ah[1][0], ah[1][1], ah[1][2], ah[1][3], L0.z, L0.w);
                mma_f16(tmp, ah[2][0], ah[2][1], ah[2][2], ah[2][3], L1.x, L1.y);
                mma_f16(tmp, ah[3][0], ah[3][1], ah[3][2], ah[3][3], L1.z, L1.w);
#pragma unroll
                for (int j = 0; j < 4; j++)
                    dacc[t][j] = fmaf(tmp[j], 0.00390625f, dacc[t][j]);   // 2^-8
            }

            if (l < 2) {
#pragma unroll
                for (int s = 0; s < 4; s++) {
                    const int ta = 2 * s, tb = 2 * s + 1;
                    ah[s][0] = pk_to_f16(gelu2x_pk(pk2(dacc[ta][0], dacc[ta][1]), K));
                    ah[s][1] = pk_to_f16(gelu2x_pk(pk2(dacc[ta][2], dacc[ta][3]), K));
                    ah[s][2] = pk_to_f16(gelu2x_pk(pk2(dacc[tb][0], dacc[tb][1]), K));
                    ah[s][3] = pk_to_f16(gelu2x_pk(pk2(dacc[tb][2], dacc[tb][3]), K));
                }
            } else {
                // layer 2: packed gelu2x + valid mask, warp-shuffle reduce over rows
                float v0 = smf[OFF_SVALID / 4 + r0];
                float v1 = smf[OFF_SVALID / 4 + r0 + 8];
                ull v0p = pk2(v0, v0), v1p = pk2(v1, v1);
                float sc[16];
#pragma unroll
                for (int t = 0; t < 8; t++) {
                    ull g01 = gelu2x_pk(pk2(dacc[t][0], dacc[t][1]), K);
                    ull g23 = gelu2x_pk(pk2(dacc[t][2], dacc[t][3]), K);
                    ull scp = f2fma(g01, v0p, f2mul(g23, v1p));
                    upk2(scp, sc[2 * t], sc[2 * t + 1]);
                }
#pragma unroll
                for (int off = 4; off <= 16; off <<= 1)
#pragma unroll
                    for (int i = 0; i < 16; i++)
                        sc[i] += __shfl_xor_sync(0xFFFFFFFFu, sc[i], off);
                if (lane < 4) {
#pragma unroll
                    for (int t = 0; t < 8; t++) {
                        smf[OFF_PART / 4 + w * 64 + 8 * t + 2 * lane]     = sc[2 * t];
                        smf[OFF_PART / 4 + w * 64 + 8 * t + 2 * lane + 1] = sc[2 * t + 1];
                    }
                }
            }
        }
        __syncthreads();

        // ---- combine 2 warp-partials per node, write upd, stage stats ----
        {
            int s = tid >> 6, d = tid & 63;
            float msg = smf[OFF_PART / 4 + (2 * s) * 64 + d] +
                        smf[OFF_PART / 4 + (2 * s + 1) * 64 + d];
            float upd = smf[OFF_SSELF / 4 + s * 64 + d] + msg * smf[OFF_FACT / 4 + s];
            g_upd[(size_t)(bbase + n0 + s) * 64 + d] = upd;
            smf[OFF_UPD / 4 + tid]       = upd;
            smf[OFF_UPD / 4 + 256 + tid] = upd * upd;
        }
        __syncthreads();
        // owner threads fold 4 nodes into block-local per-(b,d) stats
        if (tid < 64) {
            const float* st = smf + OFF_UPD / 4;
            float s1 = st[tid] + st[64 + tid] + st[128 + tid] + st[192 + tid];
            float s2 = st[256 + tid] + st[320 + tid] + st[384 + tid] + st[448 + tid];
            smf[OFF_SACC / 4 + b * 128 + tid]      += s1;
            smf[OFF_SACC / 4 + b * 128 + 64 + tid] += s2;
        }
    }

    // ---- flush block-local stats (all 8 batches x 64 ch x {sum,sqs}) ----
    __syncthreads();
    for (int p = tid; p < 1024; p += 256) {
        int bb2 = p >> 7;            // batch
        int rem = p & 127;           // 0..63 sum, 64..127 sqs
        float v = smf[OFF_SACC / 4 + p];
        if (rem < 64) atomicAdd(&g_sum[bb2][rem], v);
        else          atomicAdd(&g_sqs[bb2][rem - 64], v);
    }
}

// ---------------- init: zero stats + mask counts ----------------
__global__ void __launch_bounds__(256)
init_stats_kernel(const float* __restrict__ mask) {
    __shared__ float sh[256];
    const int b = blockIdx.x;
    const int tid = threadIdx.x;
    if (tid < 64) {
        g_sum[b][tid] = 0.0f;
        g_sqs[b][tid] = 0.0f;
    }
    float c = 0.0f;
    for (int i = tid; i < N_; i += 256) c += mask[b * N_ + i];
    sh[tid] = c;
    __syncthreads();
    for (int st = 128; st >= 1; st >>= 1) {
        if (tid < st) sh[tid] += sh[tid + st];
        __syncthreads();
    }
    if (tid == 0) {
        float cc = sh[0];
        g_cnt[b] = (cc == 0.0f) ? 1.0f : cc;
    }
}

__global__ void __launch_bounds__(256)
norm_kernel(const float* __restrict__ mask,
            const float* __restrict__ scale,
            const float* __restrict__ shift,
            float* __restrict__ out) {
    int t = blockIdx.x * 256 + threadIdx.x;        // 1M threads, 1 float4 each
    int bn = t >> 4;
    int b  = bn >> 13;
    int d0 = (t & 15) << 2;
    float cnt = g_cnt[b];
    float4 s1 = *reinterpret_cast<const float4*>(&g_sum[b][d0]);
    float4 s2 = *reinterpret_cast<const float4*>(&g_sqs[b][d0]);
    float4 u  = reinterpret_cast<const float4*>(g_upd)[t];
    float m   = mask[bn];
    float rc  = 1.0f / cnt;
    float4 o;
    {
        float mean = s1.x * rc;
        float var  = (s2.x - 2.0f * mean * s1.x + (float)N_ * mean * mean) * rc;
        o.x = fmaf((u.x - mean) * rsqrtf(var + 1e-5f), scale[d0 + 0], shift[d0 + 0]) * m;
    }
    {
        float mean = s1.y * rc;
        float var  = (s2.y - 2.0f * mean * s1.y + (float)N_ * mean * mean) * rc;
        o.y = fmaf((u.y - mean) * rsqrtf(var + 1e-5f), scale[d0 + 1], shift[d0 + 1]) * m;
    }
    {
        float mean = s1.z * rc;
        float var  = (s2.z - 2.0f * mean * s1.z + (float)N_ * mean * mean) * rc;
        o.z = fmaf((u.z - mean) * rsqrtf(var + 1e-5f), scale[d0 + 2], shift[d0 + 2]) * m;
    }
    {
        float mean = s1.w * rc;
        float var  = (s2.w - 2.0f * mean * s1.w + (float)N_ * mean * mean) * rc;
        o.w = fmaf((u.w - mean) * rsqrtf(var + 1e-5f), scale[d0 + 3], shift[d0 + 3]) * m;
    }
    reinterpret_cast<float4*>(out)[t] = o;
}

extern "C" void kernel_launch(void* const* d_in, const int* in_sizes, int n_in,
                              void* d_out, int out_size) {
    const float* emb   = (const float*)d_in[0];
    const float* dists = (const float*)d_in[1];
    const int*   eidx  = (const int*)d_in[2];
    const float* mask  = (const float*)d_in[3];
    const float* W0 = (const float*)d_in[4];
    const float* b0 = (const float*)d_in[5];
    const float* W1 = (const float*)d_in[6];
    const float* b1 = (const float*)d_in[7];
    const float* W2 = (const float*)d_in[8];
    const float* b2 = (const float*)d_in[9];
    const float* scale = (const float*)d_in[10];
    const float* shift = (const float*)d_in[11];
    float* out = (float*)d_out;

    int smc = 148;
    cudaDeviceGetAttribute(&smc, cudaDevAttrMultiProcessorCount, 0);

    cudaFuncSetAttribute(mpnn_msg_kernel,
                         cudaFuncAttributeMaxDynamicSharedMemorySize, SMEM_BYTES);

    init_stats_kernel<<<B_, 256>>>(mask);
    mpnn_msg_kernel<<<2 * smc, 256, SMEM_BYTES>>>(emb, dists, eidx, mask,
                                                  W0, b0, W1, b1, W2, b2);
    norm_kernel<<<(B_ * N_ * D_ / 4 + 255) / 256, 256>>>(mask, scale, shift, out);
}

// round 9
// speedup vs baseline: 3.7587x; 1.0422x over previous
#include <cuda_runtime.h>
#include <cuda_fp16.h>
#include <math.h>
#include <cstdint>

#define B_ 8
#define N_ 8192
#define K_ 32
#define D_ 64

typedef unsigned long long ull;

// ---------------- dynamic smem byte offsets ----------------
#define OFF_BFRAG   0          // B frags: 24 combos x (hi 1024B + lo 1024B), lo scaled x256; W1,W2 pre-halved
#define OFF_AGH     49152      // 128 rows x 34 uint (fp16x2 gathered src), 17408B
#define OFF_W0SELF  66560      // [64 i][64 d] f32 (self half of W0, i-major)
#define OFF_SSELF   82944      // 4 x 64 f32 (emb*mask per node)
#define OFF_SELFC   83968      // 4 x 64 f32 (b0 + self-part of layer 0)
#define OFF_SDIST   84992      // 128 f32
#define OFF_SVALID  85504      // 128 f32
#define OFF_SIDX    86016      // 128 i32
#define OFF_WD      86528      // 64 f32 (W0[:,128] dist column)
#define OFF_B1S     86784      // 64 f32
#define OFF_B2S     87040      // 64 f32
#define OFF_FACT    87296      // 4 f32 (mask*0.5/n_valid)
#define OFF_PART    87312      // 8 warps x 64 f32 partial message sums
#define OFF_UPD     89360      // 512 f32: upd staging (u at [tid], u^2 at [256+tid])
#define OFF_SACC    93456      // 8 b x 64 d x 2 f32 block-local stats accumulators
#define SMEM_BYTES  97664

// ---------------- device scratch ----------------
__device__ float g_upd[B_ * N_ * D_];
__device__ float g_sum[B_][D_];
__device__ float g_sqs[B_][D_];
__device__ float g_cnt[B_];

// ---------------- packed f32x2 helpers ----------------
__device__ __forceinline__ ull pk2(float a, float b) {
    ull r; asm("mov.b64 %0, {%1, %2};" : "=l"(r) : "f"(a), "f"(b)); return r;
}
__device__ __forceinline__ void upk2(ull v, float& a, float& b) {
    asm("mov.b64 {%0, %1}, %2;" : "=f"(a), "=f"(b) : "l"(v));
}
__device__ __forceinline__ ull f2mul(ull a, ull b) {
    ull r; asm("mul.rn.f32x2 %0, %1, %2;" : "=l"(r) : "l"(a), "l"(b)); return r;
}
__device__ __forceinline__ ull f2fma(ull a, ull b, ull c) {
    ull r; asm("fma.rn.f32x2 %0, %1, %2, %3;" : "=l"(r) : "l"(a), "l"(b), "l"(c)); return r;
}

// packed gelu constants (built once per thread)
struct GP { ull C1, C2; };

// packed 2*gelu(x) per lane via tanh form:
//   2*gelu(x) ~= x * (1 + tanh(0.79788456*x + 0.03567741*x^3))
// hw tanh.approx (1 MUFU/lane); 4 packed fma-pipe ops per pair
__device__ __forceinline__ ull gelu2x_pk(ull x, const GP& K) {
    ull xx = f2mul(x, x);
    ull c  = f2fma(xx, K.C2, K.C1);          // c1 + c2*x^2
    ull u  = f2mul(c, x);                    // tanh argument
    float u0, u1; upk2(u, u0, u1);
    float t0, t1;
    asm("tanh.approx.f32 %0, %1;" : "=f"(t0) : "f"(u0));
    asm("tanh.approx.f32 %0, %1;" : "=f"(t1) : "f"(u1));
    ull t = pk2(t0, t1);
    return f2fma(x, t, x);                   // x*(1+tanh)
}

// pack two floats to fp16x2 (first arg -> low half)
__device__ __forceinline__ uint32_t pack_f16x2(float lo, float hi) {
    uint32_t r;
    asm("cvt.rn.f16x2.f32 %0, %1, %2;" : "=r"(r) : "f"(hi), "f"(lo));
    return r;
}
// packed f32x2 -> fp16x2 (low lane -> low half)
__device__ __forceinline__ uint32_t pk_to_f16(ull v) {
    float a, b; upk2(v, a, b);
    return pack_f16x2(a, b);
}

__device__ __forceinline__ void mma_f16(float* d,
                                        uint32_t a0, uint32_t a1, uint32_t a2, uint32_t a3,
                                        uint32_t b0, uint32_t b1) {
    asm volatile(
        "mma.sync.aligned.m16n8k16.row.col.f32.f16.f16.f32 "
        "{%0,%1,%2,%3}, {%4,%5,%6,%7}, {%8,%9}, {%0,%1,%2,%3};"
        : "+f"(d[0]), "+f"(d[1]), "+f"(d[2]), "+f"(d[3])
        : "r"(a0), "r"(a1), "r"(a2), "r"(a3), "r"(b0), "r"(b1));
}

__global__ void __launch_bounds__(256, 2)
mpnn_msg_kernel(const float* __restrict__ emb,
                const float* __restrict__ dists,
                const int*   __restrict__ eidx,
                const float* __restrict__ mask,
                const float* __restrict__ W0, const float* __restrict__ b0,
                const float* __restrict__ W1, const float* __restrict__ b1,
                const float* __restrict__ W2, const float* __restrict__ b2)
{
    extern __shared__ char smb[];
    float* smf = reinterpret_cast<float*>(smb);
    const int tid = threadIdx.x;
    const int w = tid >> 5, lane = tid & 31;
    const int lq = lane >> 2;      // 0..7 (row group)
    const int lr = lane & 3;       // 0..3 (col pair group)

    GP K;
    K.C1 = pk2(0.7978845608f, 0.7978845608f);
    K.C2 = pk2(0.03567740814f, 0.03567740814f);

    // ---- one-time staging ----
    // B fragments; layers 1,2 pre-scaled by 0.5 (gelu2x emits 2*gelu)
    for (int c = w; c < 24; c += 8) {
        const int l = c >> 3, t = c & 7;
        const float* W = (l == 0) ? W0 : (l == 1) ? W1 : W2;
        const int stride = (l == 0) ? 129 : 64;
        const float wsc = (l == 0) ? 1.0f : 0.5f;
        const int n = t * 8 + lq;
        uint32_t hi[8], lo[8];
#pragma unroll
        for (int j = 0; j < 8; j++) {
            int s = j >> 1, rsel = j & 1;
            int k = 16 * s + 8 * rsel + 2 * lr;
            float x0 = W[n * stride + k] * wsc;
            float x1 = W[n * stride + k + 1] * wsc;
            uint32_t h = pack_f16x2(x0, x1);
            __half2 hh = *reinterpret_cast<__half2*>(&h);
            float r0f = x0 - __low2float(hh);
            float r1f = x1 - __high2float(hh);
            hi[j] = h;
            lo[j] = pack_f16x2(r0f * 256.0f, r1f * 256.0f);
        }
        uint4* dh = reinterpret_cast<uint4*>(smb + OFF_BFRAG + c * 2048 + lane * 32);
        uint4* dl = reinterpret_cast<uint4*>(smb + OFF_BFRAG + c * 2048 + 1024 + lane * 32);
        dh[0] = make_uint4(hi[0], hi[1], hi[2], hi[3]);
        dh[1] = make_uint4(hi[4], hi[5], hi[6], hi[7]);
        dl[0] = make_uint4(lo[0], lo[1], lo[2], lo[3]);
        dl[1] = make_uint4(lo[4], lo[5], lo[6], lo[7]);
    }
    for (int p = tid; p < 4096; p += 256) {
        int i = p >> 6, d = p & 63;
        smf[OFF_W0SELF / 4 + p] = W0[d * 129 + 64 + i];
    }
    if (tid < 64) {
        smf[OFF_WD / 4 + tid]  = W0[tid * 129 + 128];
        smf[OFF_B1S / 4 + tid] = b1[tid];
        smf[OFF_B2S / 4 + tid] = b2[tid];
    }
    // zero block-local stats accumulators
    for (int p = tid; p < 1024; p += 256) smf[OFF_SACC / 4 + p] = 0.0f;
    __syncthreads();

    int* sIdx = reinterpret_cast<int*>(smb + OFF_SIDX);
    const int totalTiles = (B_ * N_) / 4;   // 4 nodes x 32 edges = 128 rows/tile

    for (int tile = blockIdx.x; tile < totalTiles; tile += gridDim.x) {
        const int bn0 = tile << 2;
        const int b   = bn0 >> 13;
        const int n0  = bn0 & (N_ - 1);
        const int bbase = b * N_;

        // ---- phase 1: edge meta + masked self embedding ----
        if (tid < 128) {
            int off = (bbase + n0 + (tid >> 5)) * K_ + (tid & 31);
            int idx = eidx[off];
            smf[OFF_SVALID / 4 + tid] = (idx != -1) ? 1.0f : 0.0f;
            sIdx[tid] = (idx == -1) ? 0 : idx;
            smf[OFF_SDIST / 4 + tid] = dists[off];
        }
        {
            int s = tid >> 6, i = tid & 63;
            int row = bbase + n0 + s;
            smf[OFF_SSELF / 4 + tid] = emb[row * 64 + i] * mask[row];
        }
        __syncthreads();

        // ---- phase 2: gather src rows (fp16x2) + selfC + fact ----
#pragma unroll
        for (int q = 0; q < 8; q++) {
            int p = tid + q * 256;
            int row = p >> 4, c4 = p & 15;
            int gr = bbase + sIdx[row];
            float m = mask[gr];
            float4 v = reinterpret_cast<const float4*>(emb)[(size_t)gr * 16 + c4];
            uint2 pk;
            pk.x = pack_f16x2(v.x * m, v.y * m);
            pk.y = pack_f16x2(v.z * m, v.w * m);
            reinterpret_cast<uint2*>(smb + OFF_AGH)[row * 17 + c4] = pk;
        }
        {
            int s = tid >> 6, d = tid & 63;
            float a = b0[d];
            const float* sv = smf + OFF_SSELF / 4 + s * 64;
            const float* wp = smf + OFF_W0SELF / 4 + d;
#pragma unroll 8
            for (int i = 0; i < 64; i++) a = fmaf(sv[i], wp[i * 64], a);
            smf[OFF_SELFC / 4 + tid] = a;
        }
        if (tid < 4) {
            float c = 0.0f;
            for (int e = 0; e < 32; e++) c += smf[OFF_SVALID / 4 + tid * 32 + e];
            if (c == 0.0f) c = 1.0f;
            smf[OFF_FACT / 4 + tid] = mask[bbase + n0 + tid] * 0.5f / c;
        }
        __syncthreads();

        // ---- build layer-0 A fragments (fp16, single-rounded) ----
        const int r0 = (w << 4) + lq;      // warp's first row + row group
        uint32_t ah[4][4];
        {
            const uint32_t* agh = reinterpret_cast<const uint32_t*>(smb + OFF_AGH);
#pragma unroll
            for (int s = 0; s < 4; s++) {
                int c2 = 8 * s + lr;
                ah[s][0] = agh[r0 * 34 + c2];
                ah[s][1] = agh[(r0 + 8) * 34 + c2];
                ah[s][2] = agh[r0 * 34 + c2 + 4];
                ah[s][3] = agh[(r0 + 8) * 34 + c2 + 4];
            }
        }

        // ---- 3 layers: 2-pass fp16 MMA + packed register epilogue ----
#pragma unroll
        for (int l = 0; l < 3; l++) {
            float dacc[8][4];
            // accumulator init carries bias / selfC+dist terms
            if (l == 0) {
                const int node = w >> 1;
                float dr0 = smf[OFF_SDIST / 4 + r0];
                float dr1 = smf[OFF_SDIST / 4 + r0 + 8];
#pragma unroll
                for (int t = 0; t < 8; t++) {
                    const int c0 = 8 * t + 2 * lr;
                    float sc0 = smf[OFF_SELFC / 4 + node * 64 + c0];
                    float sc1 = smf[OFF_SELFC / 4 + node * 64 + c0 + 1];
                    float wd0 = smf[OFF_WD / 4 + c0];
                    float wd1 = smf[OFF_WD / 4 + c0 + 1];
                    dacc[t][0] = fmaf(dr0, wd0, sc0);
                    dacc[t][1] = fmaf(dr0, wd1, sc1);
                    dacc[t][2] = fmaf(dr1, wd0, sc0);
                    dacc[t][3] = fmaf(dr1, wd1, sc1);
                }
            } else {
                const float* bb = smf + ((l == 1) ? OFF_B1S : OFF_B2S) / 4;
#pragma unroll
                for (int t = 0; t < 8; t++) {
                    const int c0 = 8 * t + 2 * lr;
                    float b0v = bb[c0], b1v = bb[c0 + 1];
                    dacc[t][0] = b0v; dacc[t][2] = b0v;
                    dacc[t][1] = b1v; dacc[t][3] = b1v;
                }
            }

#pragma unroll
            for (int t = 0; t < 8; t++) {
                const char* base = smb + OFF_BFRAG + (l * 8 + t) * 2048;
                const uint4* bph = reinterpret_cast<const uint4*>(base + lane * 32);
                uint4 h0 = bph[0], h1 = bph[1];
                mma_f16(dacc[t], ah[0][0], ah[0][1], ah[0][2], ah[0][3], h0.x, h0.y);
                mma_f16(dacc[t], ah[1][0], ah[1][1], ah[1][2], ah[1][3], h0.z, h0.w);
                mma_f16(dacc[t], ah[2][0], ah[2][1], ah[2][2], ah[2][3], h1.x, h1.y);
                mma_f16(dacc[t], ah[3][0], ah[3][1], ah[3][2], ah[3][3], h1.z, h1.w);
                const uint4* bpl = reinterpret_cast<const uint4*>(base + 1024 + lane * 32);
                uint4 L0 = bpl[0], L1 = bpl[1];
                float tmp[4] = {0.0f, 0.0f, 0.0f, 0.0f};
                mma_f16(tmp, ah[0][0], ah[0][1], ah[0][2], ah[0][3], L0.x, L0.y);
                mma_f16(tmp, ah[1][0], ah[1][1], ah[1][2], ah[1][3], L0.z, L0.w);
                mma_f16(tmp, ah[2][0], ah[2][1], ah[2][2], ah[2][3], L1.x, L1.y);
                mma_f16(tmp, ah[3][0], ah[3][1], ah[3][2], ah[3][3], L1.z, L1.w);
#pragma unroll
                for (int j = 0; j < 4; j++)
                    dacc[t][j] = fmaf(tmp[j], 0.00390625f, dacc[t][j]);   // 2^-8
            }

            if (l < 2) {
#pragma unroll
                for (int s = 0; s < 4; s++) {
                    const int ta = 2 * s, tb = 2 * s + 1;
                    ah[s][0] = pk_to_f16(gelu2x_pk(pk2(dacc[ta][0], dacc[ta][1]), K));
                    ah[s][1] = pk_to_f16(gelu2x_pk(pk2(dacc[ta][2], dacc[ta][3]), K));
                    ah[s][2] = pk_to_f16(gelu2x_pk(pk2(dacc[tb][0], dacc[tb][1]), K));
                    ah[s][3] = pk_to_f16(gelu2x_pk(pk2(dacc[tb][2], dacc[tb][3]), K));
                }
            } else {
                // layer 2: packed gelu2x + valid mask, warp-shuffle reduce over rows
                float v0 = smf[OFF_SVALID / 4 + r0];
                float v1 = smf[OFF_SVALID / 4 + r0 + 8];
                ull v0p = pk2(v0, v0), v1p = pk2(v1, v1);
                float sc[16];
#pragma unroll
                for (int t = 0; t < 8; t++) {
                    ull g01 = gelu2x_pk(pk2(dacc[t][0], dacc[t][1]), K);
                    ull g23 = gelu2x_pk(pk2(dacc[t][2], dacc[t][3]), K);
                    ull scp = f2fma(g01, v0p, f2mul(g23, v1p));
                    upk2(scp, sc[2 * t], sc[2 * t + 1]);
                }
#pragma unroll
                for (int off = 4; off <= 16; off <<= 1)
#pragma unroll
                    for (int i = 0; i < 16; i++)
                        sc[i] += __shfl_xor_sync(0xFFFFFFFFu, sc[i], off);
                if (lane < 4) {
#pragma unroll
                    for (int t = 0; t < 8; t++) {
                        smf[OFF_PART / 4 + w * 64 + 8 * t + 2 * lane]     = sc[2 * t];
                        smf[OFF_PART / 4 + w * 64 + 8 * t + 2 * lane + 1] = sc[2 * t + 1];
                    }
                }
            }
        }
        __syncthreads();

        // ---- combine 2 warp-partials per node, write upd, stage stats ----
        {
            int s = tid >> 6, d = tid & 63;
            float msg = smf[OFF_PART / 4 + (2 * s) * 64 + d] +
                        smf[OFF_PART / 4 + (2 * s + 1) * 64 + d];
            float upd = smf[OFF_SSELF / 4 + s * 64 + d] + msg * smf[OFF_FACT / 4 + s];
            g_upd[(size_t)(bbase + n0 + s) * 64 + d] = upd;
            smf[OFF_UPD / 4 + tid]       = upd;
            smf[OFF_UPD / 4 + 256 + tid] = upd * upd;
        }
        __syncthreads();
        // owner threads fold 4 nodes into block-local per-(b,d) stats
        if (tid < 64) {
            const float* st = smf + OFF_UPD / 4;
            float s1 = st[tid] + st[64 + tid] + st[128 + tid] + st[192 + tid];
            float s2 = st[256 + tid] + st[320 + tid] + st[384 + tid] + st[448 + tid];
            smf[OFF_SACC / 4 + b * 128 + tid]      += s1;
            smf[OFF_SACC / 4 + b * 128 + 64 + tid] += s2;
        }
    }

    // ---- flush block-local stats (all 8 batches x 64 ch x {sum,sqs}) ----
    __syncthreads();
    for (int p = tid; p < 1024; p += 256) {
        int bb2 = p >> 7;            // batch
        int rem = p & 127;           // 0..63 sum, 64..127 sqs
        float v = smf[OFF_SACC / 4 + p];
        if (rem < 64) atomicAdd(&g_sum[bb2][rem], v);
        else          atomicAdd(&g_sqs[bb2][rem - 64], v);
    }
}

// ---------------- init: zero stats + mask counts ----------------
__global__ void __launch_bounds__(256)
init_stats_kernel(const float* __restrict__ mask) {
    __shared__ float sh[256];
    const int b = blockIdx.x;
    const int tid = threadIdx.x;
    if (tid < 64) {
        g_sum[b][tid] = 0.0f;
        g_sqs[b][tid] = 0.0f;
    }
    float c = 0.0f;
    for (int i = tid; i < N_; i += 256) c += mask[b * N_ + i];
    sh[tid] = c;
    __syncthreads();
    for (int st = 128; st >= 1; st >>= 1) {
        if (tid < st) sh[tid] += sh[tid + st];
        __syncthreads();
    }
    if (tid == 0) {
        float cc = sh[0];
        g_cnt[b] = (cc == 0.0f) ? 1.0f : cc;
    }
}

__global__ void __launch_bounds__(256)
norm_kernel(const float* __restrict__ mask,
            const float* __restrict__ scale,
            const float* __restrict__ shift,
            float* __restrict__ out) {
    int t = blockIdx.x * 256 + threadIdx.x;        // 1M threads, 1 float4 each
    int bn = t >> 4;
    int b  = bn >> 13;
    int d0 = (t & 15) << 2;
    float cnt = g_cnt[b];
    float4 s1 = *reinterpret_cast<const float4*>(&g_sum[b][d0]);
    float4 s2 = *reinterpret_cast<const float4*>(&g_sqs[b][d0]);
    float4 u  = reinterpret_cast<const float4*>(g_upd)[t];
    float m   = mask[bn];
    float rc  = 1.0f / cnt;
    float4 o;
    {
        float mean = s1.x * rc;
        float var  = (s2.x - 2.0f * mean * s1.x + (float)N_ * mean * mean) * rc;
        o.x = fmaf((u.x - mean) * rsqrtf(var + 1e-5f), scale[d0 + 0], shift[d0 + 0]) * m;
    }
    {
        float mean = s1.y * rc;
        float var  = (s2.y - 2.0f * mean * s1.y + (float)N_ * mean * mean) * rc;
        o.y = fmaf((u.y - mean) * rsqrtf(var + 1e-5f), scale[d0 + 1], shift[d0 + 1]) * m;
    }
    {
        float mean = s1.z * rc;
        float var  = (s2.z - 2.0f * mean * s1.z + (float)N_ * mean * mean) * rc;
        o.z = fmaf((u.z - mean) * rsqrtf(var + 1e-5f), scale[d0 + 2], shift[d0 + 2]) * m;
    }
    {
        float mean = s1.w * rc;
        float var  = (s2.w - 2.0f * mean * s1.w + (float)N_ * mean * mean) * rc;
        o.w = fmaf((u.w - mean) * rsqrtf(var + 1e-5f), scale[d0 + 3], shift[d0 + 3]) * m;
    }
    reinterpret_cast<float4*>(out)[t] = o;
}

extern "C" void kernel_launch(void* const* d_in, const int* in_sizes, int n_in,
                              void* d_out, int out_size) {
    const float* emb   = (const float*)d_in[0];
    const float* dists = (const float*)d_in[1];
    const int*   eidx  = (const int*)d_in[2];
    const float* mask  = (const float*)d_in[3];
    const float* W0 = (const float*)d_in[4];
    const float* b0 = (const float*)d_in[5];
    const float* W1 = (const float*)d_in[6];
    const float* b1 = (const float*)d_in[7];
    const float* W2 = (const float*)d_in[8];
    const float* b2 = (const float*)d_in[9];
    const float* scale = (const float*)d_in[10];
    const float* shift = (const float*)d_in[11];
    float* out = (float*)d_out;

    int smc = 148;
    cudaDeviceGetAttribute(&smc, cudaDevAttrMultiProcessorCount, 0);

    cudaFuncSetAttribute(mpnn_msg_kernel,
                         cudaFuncAttributeMaxDynamicSharedMemorySize, SMEM_BYTES);

    init_stats_kernel<<<B_, 256>>>(mask);
    mpnn_msg_kernel<<<2 * smc, 256, SMEM_BYTES>>>(emb, dists, eidx, mask,
                                                  W0, b0, W1, b1, W2, b2);
    norm_kernel<<<(B_ * N_ * D_ / 4 + 255) / 256, 256>>>(mask, scale, shift, out);
}

// round 10
// speedup vs baseline: 4.8363x; 1.2867x over previous
#include <cuda_runtime.h>
#include <cuda_fp16.h>
#include <math.h>
#include <cstdint>

#define B_ 8
#define N_ 8192
#define K_ 32
#define D_ 64

typedef unsigned long long ull;

// ---------------- dynamic smem byte offsets ----------------
#define OFF_BFRAG   0          // B frags: 24 combos x (hi 1024B + lo 1024B), lo scaled x256; W1,W2 pre-halved
#define OFF_AGH     49152      // 256 rows x 34 uint (fp16x2 gathered src), 34816B ; UPD aliases this
#define OFF_SSELF   83968      // 8 x 64 f32 (emb*mask per node)
#define OFF_SELFC   86016      // 8 x 64 f32 (b0 + self-part of layer 0, precomputed)
#define OFF_SDIST   88064      // 256 f32
#define OFF_SVALID  89088      // 256 f32
#define OFF_SIDX    90112      // 256 i32
#define OFF_WD      91136      // 64 f32 (W0[:,128] dist column)
#define OFF_B1S     91392      // 64 f32
#define OFF_B2S     91648      // 64 f32
#define OFF_FACT    91904      // 8 f32 (mask*0.5/n_valid)
#define OFF_PART    91936      // 8 nodes x 64 f32 full per-node message sums
#define OFF_SACC    93984      // 8 b x 64 d x 2 f32 block-local stats accumulators
#define SMEM_BYTES  98304

#define OFF_UPD     OFF_AGH    // 1024 f32 staging (aliases AGH, dead by then)

// ---------------- device scratch ----------------
__device__ float g_upd[B_ * N_ * D_];
__device__ float g_selfc[B_ * N_ * D_];
__device__ float g_sum[B_][D_];
__device__ float g_sqs[B_][D_];
__device__ float g_cnt[B_];

// ---------------- packed f32x2 helpers ----------------
__device__ __forceinline__ ull pk2(float a, float b) {
    ull r; asm("mov.b64 %0, {%1, %2};" : "=l"(r) : "f"(a), "f"(b)); return r;
}
__device__ __forceinline__ void upk2(ull v, float& a, float& b) {
    asm("mov.b64 {%0, %1}, %2;" : "=f"(a), "=f"(b) : "l"(v));
}
__device__ __forceinline__ ull f2mul(ull a, ull b) {
    ull r; asm("mul.rn.f32x2 %0, %1, %2;" : "=l"(r) : "l"(a), "l"(b)); return r;
}
__device__ __forceinline__ ull f2fma(ull a, ull b, ull c) {
    ull r; asm("fma.rn.f32x2 %0, %1, %2, %3;" : "=l"(r) : "l"(a), "l"(b), "l"(c)); return r;
}

// packed gelu constants
struct GP { ull C1, C2; };

// packed 2*gelu(x): x * (1 + tanh(0.79788456*x + 0.03567741*x^3)), hw tanh
__device__ __forceinline__ ull gelu2x_pk(ull x, const GP& K) {
    ull xx = f2mul(x, x);
    ull c  = f2fma(xx, K.C2, K.C1);
    ull u  = f2mul(c, x);
    float u0, u1; upk2(u, u0, u1);
    float t0, t1;
    asm("tanh.approx.f32 %0, %1;" : "=f"(t0) : "f"(u0));
    asm("tanh.approx.f32 %0, %1;" : "=f"(t1) : "f"(u1));
    ull t = pk2(t0, t1);
    return f2fma(x, t, x);
}

__device__ __forceinline__ uint32_t pack_f16x2(float lo, float hi) {
    uint32_t r;
    asm("cvt.rn.f16x2.f32 %0, %1, %2;" : "=r"(r) : "f"(hi), "f"(lo));
    return r;
}
__device__ __forceinline__ uint32_t pk_to_f16(ull v) {
    float a, b; upk2(v, a, b);
    return pack_f16x2(a, b);
}

__device__ __forceinline__ void mma_f16(float* d,
                                        uint32_t a0, uint32_t a1, uint32_t a2, uint32_t a3,
                                        uint32_t b0, uint32_t b1) {
    asm volatile(
        "mma.sync.aligned.m16n8k16.row.col.f32.f16.f16.f32 "
        "{%0,%1,%2,%3}, {%4,%5,%6,%7}, {%8,%9}, {%0,%1,%2,%3};"
        : "+f"(d[0]), "+f"(d[1]), "+f"(d[2]), "+f"(d[3])
        : "r"(a0), "r"(a1), "r"(a2), "r"(a3), "r"(b0), "r"(b1));
}

__global__ void __launch_bounds__(256, 2)
mpnn_msg_kernel(const float* __restrict__ emb,
                const float* __restrict__ dists,
                const int*   __restrict__ eidx,
                const float* __restrict__ mask,
                const float* __restrict__ W0, const float* __restrict__ b0,
                const float* __restrict__ W1, const float* __restrict__ b1,
                const float* __restrict__ W2, const float* __restrict__ b2)
{
    extern __shared__ char smb[];
    float* smf = reinterpret_cast<float*>(smb);
    const int tid = threadIdx.x;
    const int w = tid >> 5, lane = tid & 31;
    const int lq = lane >> 2;      // 0..7 (row group)
    const int lr = lane & 3;       // 0..3 (col pair group)

    GP K;
    K.C1 = pk2(0.7978845608f, 0.7978845608f);
    K.C2 = pk2(0.03567740814f, 0.03567740814f);

    // ---- one-time staging: B fragments (fp16 hi + lo*256), wd, biases ----
    for (int c = w; c < 24; c += 8) {
        const int l = c >> 3, t = c & 7;
        const float* W = (l == 0) ? W0 : (l == 1) ? W1 : W2;
        const int stride = (l == 0) ? 129 : 64;
        const float wsc = (l == 0) ? 1.0f : 0.5f;
        const int n = t * 8 + lq;
        uint32_t hi[8], lo[8];
#pragma unroll
        for (int j = 0; j < 8; j++) {
            int s = j >> 1, rsel = j & 1;
            int k = 16 * s + 8 * rsel + 2 * lr;
            float x0 = W[n * stride + k] * wsc;
            float x1 = W[n * stride + k + 1] * wsc;
            uint32_t h = pack_f16x2(x0, x1);
            __half2 hh = *reinterpret_cast<__half2*>(&h);
            float r0f = x0 - __low2float(hh);
            float r1f = x1 - __high2float(hh);
            hi[j] = h;
            lo[j] = pack_f16x2(r0f * 256.0f, r1f * 256.0f);
        }
        uint4* dh = reinterpret_cast<uint4*>(smb + OFF_BFRAG + c * 2048 + lane * 32);
        uint4* dl = reinterpret_cast<uint4*>(smb + OFF_BFRAG + c * 2048 + 1024 + lane * 32);
        dh[0] = make_uint4(hi[0], hi[1], hi[2], hi[3]);
        dh[1] = make_uint4(hi[4], hi[5], hi[6], hi[7]);
        dl[0] = make_uint4(lo[0], lo[1], lo[2], lo[3]);
        dl[1] = make_uint4(lo[4], lo[5], lo[6], lo[7]);
    }
    if (tid < 64) {
        smf[OFF_WD / 4 + tid]  = W0[tid * 129 + 128];
        smf[OFF_B1S / 4 + tid] = b1[tid];
        smf[OFF_B2S / 4 + tid] = b2[tid];
    }
    for (int p = tid; p < 1024; p += 256) smf[OFF_SACC / 4 + p] = 0.0f;
    __syncthreads();

    int* sIdx = reinterpret_cast<int*>(smb + OFF_SIDX);
    const int totalTiles = (B_ * N_) / 8;   // 8 nodes x 32 edges = 256 rows/tile

    for (int tile = blockIdx.x; tile < totalTiles; tile += gridDim.x) {
        const int bn0 = tile << 3;
        const int b   = bn0 >> 13;
        const int n0  = bn0 & (N_ - 1);
        const int bbase = b * N_;

        // ---- phase 1: edge meta + self emb + precomputed selfC ----
        {
            int off = (bbase + n0 + (tid >> 5)) * K_ + (tid & 31);
            int idx = eidx[off];
            smf[OFF_SVALID / 4 + tid] = (idx != -1) ? 1.0f : 0.0f;
            sIdx[tid] = (idx == -1) ? 0 : idx;
            smf[OFF_SDIST / 4 + tid] = dists[off];
        }
#pragma unroll
        for (int q = 0; q < 2; q++) {
            int idx = tid + q * 256;
            int s = idx >> 6, i = idx & 63;
            int row = bbase + n0 + s;
            smf[OFF_SSELF / 4 + idx] = emb[row * 64 + i] * mask[row];
            smf[OFF_SELFC / 4 + idx] = g_selfc[(size_t)(bbase + n0) * 64 + idx];
        }
        __syncthreads();

        // ---- phase 2: gather 256 src rows (fp16x2) + fact ----
#pragma unroll
        for (int q = 0; q < 16; q++) {
            int p = tid + q * 256;
            int row = p >> 4, c4 = p & 15;
            int gr = bbase + sIdx[row];
            float m = mask[gr];
            float4 v4 = reinterpret_cast<const float4*>(emb)[(size_t)gr * 16 + c4];
            uint2 pk;
            pk.x = pack_f16x2(v4.x * m, v4.y * m);
            pk.y = pack_f16x2(v4.z * m, v4.w * m);
            reinterpret_cast<uint2*>(smb + OFF_AGH)[row * 17 + c4] = pk;
        }
        if (tid < 8) {
            float c = 0.0f;
            for (int e = 0; e < 32; e++) c += smf[OFF_SVALID / 4 + tid * 32 + e];
            if (c == 0.0f) c = 1.0f;
            smf[OFF_FACT / 4 + tid] = mask[bbase + n0 + tid] * 0.5f / c;
        }
        __syncthreads();

        // ---- per-warp row metadata (warp w owns node w: rows 32w..32w+31) ----
        float dr[4], vv[4];
        {
            int rb = w * 32 + lq;
            dr[0] = smf[OFF_SDIST / 4 + rb];
            dr[1] = smf[OFF_SDIST / 4 + rb + 8];
            dr[2] = smf[OFF_SDIST / 4 + rb + 16];
            dr[3] = smf[OFF_SDIST / 4 + rb + 24];
            vv[0] = smf[OFF_SVALID / 4 + rb];
            vv[1] = smf[OFF_SVALID / 4 + rb + 8];
            vv[2] = smf[OFF_SVALID / 4 + rb + 16];
            vv[3] = smf[OFF_SVALID / 4 + rb + 24];
        }

        // ---- layer-0 A fragments: 2 m-tiles of 16 rows ----
        uint32_t ah[2][4][4];
        {
            const uint32_t* agh = reinterpret_cast<const uint32_t*>(smb + OFF_AGH);
#pragma unroll
            for (int mt = 0; mt < 2; mt++) {
                int rbase = w * 32 + mt * 16 + lq;
#pragma unroll
                for (int s = 0; s < 4; s++) {
                    int c2 = 8 * s + lr;
                    ah[mt][s][0] = agh[rbase * 34 + c2];
                    ah[mt][s][1] = agh[(rbase + 8) * 34 + c2];
                    ah[mt][s][2] = agh[rbase * 34 + c2 + 4];
                    ah[mt][s][3] = agh[(rbase + 8) * 34 + c2 + 4];
                }
            }
        }

        // ---- 3 layers, B fragments shared across both m-tiles ----
        float sc[16];
#pragma unroll
        for (int l = 0; l < 3; l++) {
            uint32_t ahn[2][4][4];
            if (l == 2) {
#pragma unroll
                for (int i = 0; i < 16; i++) sc[i] = 0.0f;
            }
#pragma unroll
            for (int s = 0; s < 4; s++) {
#pragma unroll
                for (int half = 0; half < 2; half++) {
                    const int t = 2 * s + half;
                    const char* base = smb + OFF_BFRAG + (l * 8 + t) * 2048;
                    const uint4* bph = reinterpret_cast<const uint4*>(base + lane * 32);
                    uint4 h0 = bph[0], h1 = bph[1];
                    const uint4* bpl = reinterpret_cast<const uint4*>(base + 1024 + lane * 32);
                    uint4 L0 = bpl[0], L1 = bpl[1];
                    const int c0 = 8 * t + 2 * lr;
#pragma unroll
                    for (int mt = 0; mt < 2; mt++) {
                        float dacc[4];
                        if (l == 0) {
                            float s0 = smf[OFF_SELFC / 4 + w * 64 + c0];
                            float s1 = smf[OFF_SELFC / 4 + w * 64 + c0 + 1];
                            float wd0 = smf[OFF_WD / 4 + c0];
                            float wd1 = smf[OFF_WD / 4 + c0 + 1];
                            dacc[0] = fmaf(dr[2 * mt], wd0, s0);
                            dacc[1] = fmaf(dr[2 * mt], wd1, s1);
                            dacc[2] = fmaf(dr[2 * mt + 1], wd0, s0);
                            dacc[3] = fmaf(dr[2 * mt + 1], wd1, s1);
                        } else {
                            const float* bb = smf + ((l == 1) ? OFF_B1S : OFF_B2S) / 4;
                            float b0v = bb[c0], b1v = bb[c0 + 1];
                            dacc[0] = b0v; dacc[1] = b1v;
                            dacc[2] = b0v; dacc[3] = b1v;
                        }
                        mma_f16(dacc, ah[mt][0][0], ah[mt][0][1], ah[mt][0][2], ah[mt][0][3], h0.x, h0.y);
                        mma_f16(dacc, ah[mt][1][0], ah[mt][1][1], ah[mt][1][2], ah[mt][1][3], h0.z, h0.w);
                        mma_f16(dacc, ah[mt][2][0], ah[mt][2][1], ah[mt][2][2], ah[mt][2][3], h1.x, h1.y);
                        mma_f16(dacc, ah[mt][3][0], ah[mt][3][1], ah[mt][3][2], ah[mt][3][3], h1.z, h1.w);
                        float tmp[4] = {0.0f, 0.0f, 0.0f, 0.0f};
                        mma_f16(tmp, ah[mt][0][0], ah[mt][0][1], ah[mt][0][2], ah[mt][0][3], L0.x, L0.y);
                        mma_f16(tmp, ah[mt][1][0], ah[mt][1][1], ah[mt][1][2], ah[mt][1][3], L0.z, L0.w);
                        mma_f16(tmp, ah[mt][2][0], ah[mt][2][1], ah[mt][2][2], ah[mt][2][3], L1.x, L1.y);
                        mma_f16(tmp, ah[mt][3][0], ah[mt][3][1], ah[mt][3][2], ah[mt][3][3], L1.z, L1.w);
#pragma unroll
                        for (int j = 0; j < 4; j++)
                            dacc[j] = fmaf(tmp[j], 0.00390625f, dacc[j]);   // 2^-8

                        ull g01 = gelu2x_pk(pk2(dacc[0], dacc[1]), K);
                        ull g23 = gelu2x_pk(pk2(dacc[2], dacc[3]), K);
                        if (l < 2) {
                            ahn[mt][s][2 * half]     = pk_to_f16(g01);
                            ahn[mt][s][2 * half + 1] = pk_to_f16(g23);
                        } else {
                            ull vp0 = pk2(vv[2 * mt], vv[2 * mt]);
                            ull vp1 = pk2(vv[2 * mt + 1], vv[2 * mt + 1]);
                            ull scp = f2fma(g01, vp0, f2mul(g23, vp1));
                            float a0, a1; upk2(scp, a0, a1);
                            sc[2 * t]     += a0;
                            sc[2 * t + 1] += a1;
                        }
                    }
                }
            }
            if (l < 2) {
#pragma unroll
                for (int mt = 0; mt < 2; mt++)
#pragma unroll
                    for (int s = 0; s < 4; s++)
#pragma unroll
                        for (int j = 0; j < 4; j++)
                            ah[mt][s][j] = ahn[mt][s][j];
            }
        }

        // ---- warp-level reduce over the node's 32 rows ----
#pragma unroll
        for (int off = 4; off <= 16; off <<= 1)
#pragma unroll
            for (int i = 0; i < 16; i++)
                sc[i] += __shfl_xor_sync(0xFFFFFFFFu, sc[i], off);
        if (lane < 4) {
#pragma unroll
            for (int t = 0; t < 8; t++) {
                smf[OFF_PART / 4 + w * 64 + 8 * t + 2 * lane]     = sc[2 * t];
                smf[OFF_PART / 4 + w * 64 + 8 * t + 2 * lane + 1] = sc[2 * t + 1];
            }
        }
        __syncthreads();

        // ---- combine + write upd + stage stats (UPD aliases AGH) ----
#pragma unroll
        for (int q = 0; q < 2; q++) {
            int idx = tid + q * 256;
            int s = idx >> 6, d = idx & 63;
            float msg = smf[OFF_PART / 4 + s * 64 + d];
            float upd = smf[OFF_SSELF / 4 + idx] + msg * smf[OFF_FACT / 4 + s];
            g_upd[(size_t)(bbase + n0 + s) * 64 + d] = upd;
            smf[OFF_UPD / 4 + idx]       = upd;
            smf[OFF_UPD / 4 + 512 + idx] = upd * upd;
        }
        __syncthreads();
        if (tid < 64) {
            const float* st = smf + OFF_UPD / 4;
            float s1 = 0.0f, s2 = 0.0f;
#pragma unroll
            for (int k = 0; k < 8; k++) {
                s1 += st[k * 64 + tid];
                s2 += st[512 + k * 64 + tid];
            }
            smf[OFF_SACC / 4 + b * 128 + tid]      += s1;
            smf[OFF_SACC / 4 + b * 128 + 64 + tid] += s2;
        }
    }

    // ---- flush block-local stats ----
    __syncthreads();
    for (int p = tid; p < 1024; p += 256) {
        int bb2 = p >> 7;
        int rem = p & 127;
        float v = smf[OFF_SACC / 4 + p];
        if (rem < 64) atomicAdd(&g_sum[bb2][rem], v);
        else          atomicAdd(&g_sqs[bb2][rem - 64], v);
    }
}

// ---------------- selfC precompute: b0 + self-half of layer 0 ----------------
__global__ void __launch_bounds__(256)
selfc_kernel(const float* __restrict__ emb,
             const float* __restrict__ mask,
             const float* __restrict__ W0,
             const float* __restrict__ b0) {
    __shared__ float wsm[64 * 65];    // [i][d] stride 65
    __shared__ float sself[16 * 64];
    const int tid = threadIdx.x;
    for (int p = tid; p < 4096; p += 256) {
        int d = p >> 6, i = p & 63;
        wsm[i * 65 + d] = W0[d * 129 + 64 + i];
    }
    const int bn0 = blockIdx.x * 16;
#pragma unroll
    for (int q = 0; q < 4; q++) {
        int idx = tid + q * 256;
        int nl = idx >> 6, i = idx & 63;
        int bn = bn0 + nl;
        sself[idx] = emb[bn * 64 + i] * mask[bn];
    }
    __syncthreads();
    const int d = tid & 63;
#pragma unroll
    for (int nn = 0; nn < 4; nn++) {
        int nl = (tid >> 6) + nn * 4;
        float a = b0[d];
        const float* sv = sself + nl * 64;
#pragma unroll 8
        for (int i = 0; i < 64; i++) a = fmaf(sv[i], wsm[i * 65 + d], a);
        g_selfc[(size_t)(bn0 + nl) * 64 + d] = a;
    }
}

// ---------------- init: zero stats + mask counts ----------------
__global__ void __launch_bounds__(256)
init_stats_kernel(const float* __restrict__ mask) {
    __shared__ float sh[256];
    const int b = blockIdx.x;
    const int tid = threadIdx.x;
    if (tid < 64) {
        g_sum[b][tid] = 0.0f;
        g_sqs[b][tid] = 0.0f;
    }
    float c = 0.0f;
    for (int i = tid; i < N_; i += 256) c += mask[b * N_ + i];
    sh[tid] = c;
    __syncthreads();
    for (int st = 128; st >= 1; st >>= 1) {
        if (tid < st) sh[tid] += sh[tid + st];
        __syncthreads();
    }
    if (tid == 0) {
        float cc = sh[0];
        g_cnt[b] = (cc == 0.0f) ? 1.0f : cc;
    }
}

__global__ void __launch_bounds__(256)
norm_kernel(const float* __restrict__ mask,
            const float* __restrict__ scale,
            const float* __restrict__ shift,
            float* __restrict__ out) {
    int t = blockIdx.x * 256 + threadIdx.x;
    int bn = t >> 4;
    int b  = bn >> 13;
    int d0 = (t & 15) << 2;
    float cnt = g_cnt[b];
    float4 s1 = *reinterpret_cast<const float4*>(&g_sum[b][d0]);
    float4 s2 = *reinterpret_cast<const float4*>(&g_sqs[b][d0]);
    float4 u  = reinterpret_cast<const float4*>(g_upd)[t];
    float m   = mask[bn];
    float rc  = 1.0f / cnt;
    float4 o;
    {
        float mean = s1.x * rc;
        float var  = (s2.x - 2.0f * mean * s1.x + (float)N_ * mean * mean) * rc;
        o.x = fmaf((u.x - mean) * rsqrtf(var + 1e-5f), scale[d0 + 0], shift[d0 + 0]) * m;
    }
    {
        float mean = s1.y * rc;
        float var  = (s2.y - 2.0f * mean * s1.y + (float)N_ * mean * mean) * rc;
        o.y = fmaf((u.y - mean) * rsqrtf(var + 1e-5f), scale[d0 + 1], shift[d0 + 1]) * m;
    }
    {
        float mean = s1.z * rc;
        float var  = (s2.z - 2.0f * mean * s1.z + (float)N_ * mean * mean) * rc;
        o.z = fmaf((u.z - mean) * rsqrtf(var + 1e-5f), scale[d0 + 2], shift[d0 + 2]) * m;
    }
    {
        float mean = s1.w * rc;
        float var  = (s2.w - 2.0f * mean * s1.w + (float)N_ * mean * mean) * rc;
        o.w = fmaf((u.w - mean) * rsqrtf(var + 1e-5f), scale[d0 + 3], shift[d0 + 3]) * m;
    }
    reinterpret_cast<float4*>(out)[t] = o;
}

extern "C" void kernel_launch(void* const* d_in, const int* in_sizes, int n_in,
                              void* d_out, int out_size) {
    const float* emb   = (const float*)d_in[0];
    const float* dists = (const float*)d_in[1];
    const int*   eidx  = (const int*)d_in[2];
    const float* mask  = (const float*)d_in[3];
    const float* W0 = (const float*)d_in[4];
    const float* b0 = (const float*)d_in[5];
    const float* W1 = (const float*)d_in[6];
    const float* b1 = (const float*)d_in[7];
    const float* W2 = (const float*)d_in[8];
    const float* b2 = (const float*)d_in[9];
    const float* scale = (const float*)d_in[10];
    const float* shift = (const float*)d_in[11];
    float* out = (float*)d_out;

    int smc = 148;
    cudaDeviceGetAttribute(&smc, cudaDevAttrMultiProcessorCount, 0);

    cudaFuncSetAttribute(mpnn_msg_kernel,
                         cudaFuncAttributeMaxDynamicSharedMemorySize, SMEM_BYTES);

    init_stats_kernel<<<B_, 256>>>(mask);
    selfc_kernel<<<B_ * N_ / 16, 256>>>(emb, mask, W0, b0);
    mpnn_msg_kernel<<<2 * smc, 256, SMEM_BYTES>>>(emb, dists, eidx, mask,
                                                  W0, b0, W1, b1, W2, b2);
    norm_kernel<<<(B_ * N_ * D_ / 4 + 255) / 256, 256>>>(mask, scale, shift, out);
}